// round 10
// baseline (speedup 1.0000x reference)
#include <cuda_runtime.h>
#include <cuda_bf16.h>
#include <cstdint>

#define BB 512
#define HH 1024
#define SS 64
#define TT 128

// ---------------------------------------------------------------------------
// Device-global scratch (allocation-free)
// ---------------------------------------------------------------------------
__device__ __align__(256) __nv_bfloat16 g_WoT_hi[1024 * 1024], g_WoT_lo[1024 * 1024];
__device__ __align__(256) __nv_bfloat16 g_Wc1_hi[1024 * 1024], g_Wc1_lo[1024 * 1024];
// folded attention weights
__device__ __align__(256) float g_WaF[64 * 1024];
__device__ __align__(256) float g_baF[64];
__device__ __align__(256) float g_biasGhU[4096];
// packed v4 slabs:  W slab (ntile,ks) -> 32768 B [hi|lo], rows 128 x cols 64
//                   A slab (mtile,ks) -> 16384 B [hi|lo], rows 64 x cols 64
__device__ __align__(256) char g_WihP[24 * 16 * 32768];
__device__ __align__(256) char g_WhhUP[32 * 16 * 32768];     // [Whh(3072) | WcF(1024)]
__device__ __align__(256) char g_WoP[8 * 16 * 32768];
__device__ __align__(256) char g_WcBP[8 * 16 * 32768];
__device__ __align__(256) char g_encP[(size_t)512 * 16 * 16384];
__device__ __align__(256) char g_grP[8 * 16 * 16384];
__device__ __align__(256) char g_hP[8 * 16 * 16384];
__device__ __align__(256) char g_HallP[(size_t)1024 * 16 * 16384];
// fp32 activations
__device__ __align__(256) float g_encW[(size_t)32768 * 1024];
__device__ __align__(256) float g_P[512 * 1024];
__device__ __align__(256) float g_h[512 * 1024];
__device__ __align__(256) float g_ghU[512 * 4096];           // [gh(3072) | U(1024)]
__device__ __align__(256) float g_gi[512 * 3072];
__device__ __align__(256) float g_zero[4096];

// ---------------------------------------------------------------------------
// Helpers
// ---------------------------------------------------------------------------
__device__ __forceinline__ void split2(float v, __nv_bfloat16& hi, __nv_bfloat16& lo) {
    hi = __float2bfloat16(v);
    lo = __float2bfloat16(v - __bfloat162float(hi));
}

__device__ __host__ __forceinline__ uint32_t swz(uint32_t off) {
    return off ^ ((off >> 3) & 0x70);
}
__device__ __forceinline__ size_t pa_off(int mt, int ks, int row, int col2) {
    return (size_t)(mt * 16 + ks) * 16384 + swz((uint32_t)(row * 128 + col2));
}
__device__ __forceinline__ size_t pw_off(int nt, int ks, int row, int col2) {
    return (size_t)(nt * 16 + ks) * 32768 + swz((uint32_t)(row * 128 + col2));
}

__device__ __forceinline__ uint32_t smem_u32(const void* p) {
    uint32_t a;
    asm("{ .reg .u64 t; cvta.to.shared.u64 t, %1; cvt.u32.u64 %0, t; }" : "=r"(a) : "l"(p));
    return a;
}

__device__ __forceinline__ void ldsm_x4(uint32_t* r, uint32_t addr) {
    asm volatile("ldmatrix.sync.aligned.m8n8.x4.shared.b16 {%0,%1,%2,%3}, [%4];\n"
                 : "=r"(r[0]), "=r"(r[1]), "=r"(r[2]), "=r"(r[3]) : "r"(addr));
}

__device__ __forceinline__ void mma_bf16(float* c, const uint32_t* a, const uint32_t* b) {
    asm volatile(
        "mma.sync.aligned.m16n8k16.row.col.f32.bf16.bf16.f32 "
        "{%0,%1,%2,%3}, {%4,%5,%6,%7}, {%8,%9}, {%0,%1,%2,%3};\n"
        : "+f"(c[0]), "+f"(c[1]), "+f"(c[2]), "+f"(c[3])
        : "r"(a[0]), "r"(a[1]), "r"(a[2]), "r"(a[3]), "r"(b[0]), "r"(b[1]));
}

__device__ __forceinline__ void cp16a(uint32_t dst, const void* src) {
    asm volatile("cp.async.cg.shared.global [%0], [%1], 16;\n" :: "r"(dst), "l"(src));
}
#define CP_COMMIT() asm volatile("cp.async.commit_group;\n" ::: "memory")
#define CP_WAIT1()  asm volatile("cp.async.wait_group 1;\n" ::: "memory")

#define MBAR_INIT(mb, c) asm volatile("mbarrier.init.shared.b64 [%0], %1;" :: "r"((uint32_t)(mb)), "r"((uint32_t)(c)) : "memory")
#define EXPECT_TX(mb, n) asm volatile("mbarrier.arrive.expect_tx.shared.b64 _, [%0], %1;" :: "r"((uint32_t)(mb)), "r"((uint32_t)(n)) : "memory")
#define BULK_CP(dst, src, n, mb) \
    asm volatile("cp.async.bulk.shared::cluster.global.mbarrier::complete_tx::bytes [%0], [%1], %2, [%3];" \
        :: "r"((uint32_t)(dst)), "l"(src), "r"((uint32_t)(n)), "r"((uint32_t)(mb)) : "memory")

#define MBAR_WAIT(mb, par) do { \
    uint32_t _m = (uint32_t)(mb); uint32_t _p = (uint32_t)(par); uint32_t _d; \
    asm volatile("{\n\t.reg .pred p;\n\t" \
        "mbarrier.try_wait.parity.acquire.cta.shared::cta.b64 p, [%1], %2;\n\t" \
        "selp.b32 %0, 1, 0, p;\n\t}" : "=r"(_d) : "r"(_m), "r"(_p) : "memory"); \
    if (!_d) { \
        asm volatile("{\n\t.reg .pred P1;\n\t" \
            "WL_%=:\n\t" \
            "mbarrier.try_wait.parity.acquire.cta.shared::cta.b64 P1, [%0], %1, 0x989680;\n\t" \
            "@P1 bra.uni WD_%=;\n\t" \
            "bra.uni WL_%=;\n\t" \
            "WD_%=:\n\t}" :: "r"(_m), "r"(_p) : "memory"); \
    } \
} while (0)

// ---------------------------------------------------------------------------
// Engine v3 (cp.async 16B path) — setup WcF GEMM only.
// mode 3: split output written DIRECTLY into a packed W slab (Chi = slab base,
// ldch = packed row base).
// ---------------------------------------------------------------------------
struct GProb {
    const __nv_bfloat16 *Ahi, *Alo; int lda;
    const __nv_bfloat16 *Whi, *Wlo; int ldw;
    int K;
    const float* bias;
    float* Cf; int ldc;
    __nv_bfloat16 *Chi, *Clo; int ldch;
    int mode;
};

#define ENG_ALO 9216u
#define ENG_WHI 18432u
#define ENG_WLO 36864u
#define ENG_STAGE 55296u
#define ENG_SMEM 110592

__global__ __launch_bounds__(256, 2) void gemm_std_kernel(GProb p)
{
    extern __shared__ char sm[];
    const uint32_t smbase = smem_u32(sm);
    const int tid = threadIdx.x, warp = tid >> 5, lane = tid & 31;
    const int m0 = blockIdx.y * 64, n0 = blockIdx.x * 128;
    const int S = p.K >> 6;
    const int wm = warp >> 2, wn = warp & 3;
    const int lr = tid >> 1;
    const int lc = (tid & 1) * 4;

    float acc[2][4][4];
#pragma unroll
    for (int mi = 0; mi < 2; ++mi)
#pragma unroll
        for (int nf = 0; nf < 4; ++nf)
#pragma unroll
            for (int q = 0; q < 4; ++q) acc[mi][nf][q] = 0.f;

    const __nv_bfloat16* abase = (lr < 64)
        ? p.Ahi + (size_t)(m0 + lr) * p.lda
        : p.Alo + (size_t)(m0 + lr - 64) * p.lda;
    const __nv_bfloat16* w1base = p.Whi + (size_t)(n0 + lr) * p.ldw;
    const __nv_bfloat16* w2base = p.Wlo + (size_t)(n0 + lr) * p.ldw;
    const uint32_t rowb = (uint32_t)lr * 144 + (uint32_t)lc * 16;

    auto load_stage = [&](int s) {
        const int k0 = (s << 6) + lc * 8;
        const uint32_t sb = smbase + (uint32_t)(s & 1) * ENG_STAGE;
#pragma unroll
        for (int c = 0; c < 4; ++c) cp16a(sb + rowb + c * 16, abase + k0 + c * 8);
#pragma unroll
        for (int c = 0; c < 4; ++c) cp16a(sb + ENG_WHI + rowb + c * 16, w1base + k0 + c * 8);
#pragma unroll
        for (int c = 0; c < 4; ++c) cp16a(sb + ENG_WLO + rowb + c * 16, w2base + k0 + c * 8);
    };

    load_stage(0); CP_COMMIT();
    load_stage(1); CP_COMMIT();

    const int arow = wm * 32 + (lane & 15);
    const int acolb = (lane >> 4) << 3;
    const int g = lane >> 3;
    const int brow = wn * 32 + ((g >> 1) << 3) + (lane & 7);
    const int bcolb = (g & 1) << 3;

    for (int s = 0; s < S; ++s) {
        CP_WAIT1();
        __syncthreads();
        const uint32_t sb = smbase + (uint32_t)(s & 1) * ENG_STAGE;
#pragma unroll
        for (int kk = 0; kk < 4; ++kk) {
            const int acol = kk * 16 + acolb;
            uint32_t ahi[2][4], alo[2][4];
#pragma unroll
            for (int mi = 0; mi < 2; ++mi) {
                const uint32_t off = (uint32_t)((arow + mi * 16) * 144 + acol * 2);
                ldsm_x4(ahi[mi], sb + off);
                ldsm_x4(alo[mi], sb + ENG_ALO + off);
            }
            const int bcol = kk * 16 + bcolb;
            uint32_t bhi[4][2], blo[4][2];
#pragma unroll
            for (int nh = 0; nh < 2; ++nh) {
                uint32_t r[4];
                const uint32_t off = (uint32_t)((brow + nh * 16) * 144 + bcol * 2);
                ldsm_x4(r, sb + ENG_WHI + off);
                bhi[nh * 2 + 0][0] = r[0]; bhi[nh * 2 + 0][1] = r[1];
                bhi[nh * 2 + 1][0] = r[2]; bhi[nh * 2 + 1][1] = r[3];
                ldsm_x4(r, sb + ENG_WLO + off);
                blo[nh * 2 + 0][0] = r[0]; blo[nh * 2 + 0][1] = r[1];
                blo[nh * 2 + 1][0] = r[2]; blo[nh * 2 + 1][1] = r[3];
            }
#pragma unroll
            for (int mi = 0; mi < 2; ++mi)
#pragma unroll
                for (int nf = 0; nf < 4; ++nf)
                    mma_bf16(acc[mi][nf], ahi[mi], bhi[nf]);
#pragma unroll
            for (int mi = 0; mi < 2; ++mi)
#pragma unroll
                for (int nf = 0; nf < 4; ++nf)
                    mma_bf16(acc[mi][nf], ahi[mi], blo[nf]);
#pragma unroll
            for (int mi = 0; mi < 2; ++mi)
#pragma unroll
                for (int nf = 0; nf < 4; ++nf)
                    mma_bf16(acc[mi][nf], alo[mi], bhi[nf]);
        }
        __syncthreads();
        if (s + 2 < S) load_stage(s + 2);
        CP_COMMIT();
    }

    const int row0 = m0 + wm * 32 + (lane >> 2);
    const int col0 = n0 + wn * 32 + ((lane & 3) << 1);
#pragma unroll
    for (int mi = 0; mi < 2; ++mi) {
#pragma unroll
        for (int nf = 0; nf < 4; ++nf) {
            const int col = col0 + nf * 8;
            const float b0 = p.bias[col], b1 = p.bias[col + 1];
#pragma unroll
            for (int half = 0; half < 2; ++half) {
                const int row = row0 + mi * 16 + half * 8;
                float v0 = acc[mi][nf][half * 2 + 0] + b0;
                float v1 = acc[mi][nf][half * 2 + 1] + b1;
                if (p.mode == 0) {
                    *(float2*)&p.Cf[(size_t)row * p.ldc + col] = make_float2(v0, v1);
                } else if (p.mode == 3) {
                    __nv_bfloat162 hv, lv;
                    split2(v0, hv.x, lv.x); split2(v1, hv.y, lv.y);
                    char* dst = (char*)p.Chi;
                    const int N = p.ldch + row;
                    const size_t off = pw_off(N >> 7, col >> 6, N & 127, (col & 63) * 2);
                    *(__nv_bfloat162*)(dst + off) = hv;
                    *(__nv_bfloat162*)(dst + off + 16384) = lv;
                }
            }
        }
    }
}

// ---------------------------------------------------------------------------
// v4 GEMM block body: packed operands, cp.async.bulk, K=1024 (16 stages).
// ---------------------------------------------------------------------------
#define V4_SMEM 98304

__device__ __forceinline__ void gemm4_block(
    const char* __restrict__ Apack, const char* __restrict__ Wpack,
    const float* __restrict__ bias, float* __restrict__ Cf, int ldc,
    int mtile, int ntile, uint32_t sb0, uint32_t mbb)
{
    const int tid = threadIdx.x, warp = tid >> 5, lane = tid & 31;
    const char* Ab = Apack + (size_t)mtile * 16 * 16384;
    const char* Wb = Wpack + (size_t)ntile * 16 * 32768;
    const uint32_t mb[2] = { mbb, mbb + 8 };

    if (tid == 0) { MBAR_INIT(mb[0], 1); MBAR_INIT(mb[1], 1); }
    __syncthreads();

    auto issue = [&](int s) {
        const uint32_t dst = sb0 + (uint32_t)(s & 1) * 49152u;
        EXPECT_TX(mb[s & 1], 49152u);
        BULK_CP(dst, Ab + (size_t)s * 16384, 16384u, mb[s & 1]);
        BULK_CP(dst + 16384u, Wb + (size_t)s * 32768, 32768u, mb[s & 1]);
    };
    if (tid == 0) { issue(0); issue(1); }

    const int wm = warp >> 2, wn = warp & 3;
    const int arow = wm * 32 + (lane & 15);
    const int acolb = (lane >> 4) << 3;
    const int g = lane >> 3;
    const int brow = wn * 32 + ((g >> 1) << 3) + (lane & 7);
    const int bcolb = (g & 1) << 3;

    float acc[2][4][4];
#pragma unroll
    for (int mi = 0; mi < 2; ++mi)
#pragma unroll
        for (int nf = 0; nf < 4; ++nf)
#pragma unroll
            for (int q = 0; q < 4; ++q) acc[mi][nf][q] = 0.f;

    for (int s = 0; s < 16; ++s) {
        const int b = s & 1;
        MBAR_WAIT(mb[b], (s >> 1) & 1);
        const uint32_t sa = sb0 + (uint32_t)b * 49152u;
        const uint32_t sw = sa + 16384u;
#pragma unroll
        for (int kk = 0; kk < 4; ++kk) {
            const int acol = kk * 16 + acolb;
            uint32_t ahi[2][4], alo[2][4];
#pragma unroll
            for (int mi = 0; mi < 2; ++mi) {
                const uint32_t off = swz((uint32_t)((arow + mi * 16) * 128 + acol * 2));
                ldsm_x4(ahi[mi], sa + off);
                ldsm_x4(alo[mi], sa + 8192u + off);
            }
            const int bcol = kk * 16 + bcolb;
            uint32_t bhi[4][2], blo[4][2];
#pragma unroll
            for (int nh = 0; nh < 2; ++nh) {
                uint32_t r[4];
                const uint32_t off = swz((uint32_t)((brow + nh * 16) * 128 + bcol * 2));
                ldsm_x4(r, sw + off);
                bhi[nh * 2 + 0][0] = r[0]; bhi[nh * 2 + 0][1] = r[1];
                bhi[nh * 2 + 1][0] = r[2]; bhi[nh * 2 + 1][1] = r[3];
                ldsm_x4(r, sw + 16384u + off);
                blo[nh * 2 + 0][0] = r[0]; blo[nh * 2 + 0][1] = r[1];
                blo[nh * 2 + 1][0] = r[2]; blo[nh * 2 + 1][1] = r[3];
            }
#pragma unroll
            for (int mi = 0; mi < 2; ++mi)
#pragma unroll
                for (int nf = 0; nf < 4; ++nf)
                    mma_bf16(acc[mi][nf], ahi[mi], bhi[nf]);
#pragma unroll
            for (int mi = 0; mi < 2; ++mi)
#pragma unroll
                for (int nf = 0; nf < 4; ++nf)
                    mma_bf16(acc[mi][nf], ahi[mi], blo[nf]);
#pragma unroll
            for (int mi = 0; mi < 2; ++mi)
#pragma unroll
                for (int nf = 0; nf < 4; ++nf)
                    mma_bf16(acc[mi][nf], alo[mi], bhi[nf]);
        }
        __syncthreads();
        if (tid == 0 && s + 2 < 16) issue(s + 2);
    }

    const int row0 = mtile * 64 + wm * 32 + (lane >> 2);
    const int col0 = ntile * 128 + wn * 32 + ((lane & 3) << 1);
#pragma unroll
    for (int mi = 0; mi < 2; ++mi) {
#pragma unroll
        for (int nf = 0; nf < 4; ++nf) {
            const int col = col0 + nf * 8;
            const float b0 = bias[col], b1 = bias[col + 1];
#pragma unroll
            for (int half = 0; half < 2; ++half) {
                const int row = row0 + mi * 16 + half * 8;
                *(float2*)&Cf[(size_t)row * ldc + col] =
                    make_float2(acc[mi][nf][half * 2 + 0] + b0,
                                acc[mi][nf][half * 2 + 1] + b1);
            }
        }
    }
}

// generic v4 launch wrapper; mtile = blockIdx.y * mscale + mbase
__global__ __launch_bounds__(256, 2) void gemm4_kernel(
    const char* __restrict__ Apack, const char* __restrict__ Wpack,
    const float* __restrict__ bias, float* __restrict__ Cf, int ldc,
    int mscale, int mbase)
{
    extern __shared__ char sm[];
    __shared__ uint64_t mbar[2];
    gemm4_block(Apack, Wpack, bias, Cf, ldc,
                blockIdx.y * mscale + mbase, blockIdx.x,
                smem_u32(sm), smem_u32(&mbar[0]));
}

// ---------------------------------------------------------------------------
// stepA: blocks 0..255 = ghU v4 GEMM; blocks 256..511 = attention (2 rows).
// ---------------------------------------------------------------------------
struct StepAArgs {
    const char *hP, *WhhUP;
    const float* biasG;
    float* ghU;
    const float *h, *encW, *W, *bias;
    int wld;
    float* P;
};

__global__ __launch_bounds__(256, 2) void stepA_kernel(StepAArgs a)
{
    extern __shared__ char sm[];
    __shared__ uint64_t mbar[2];
    __shared__ float sh[2][1024];
    __shared__ float slog[2][64];
    __shared__ float sw[2][64];

    const int bid = blockIdx.x;
    if (bid < 256) {
        gemm4_block(a.hP, a.WhhUP, a.biasG, a.ghU, 4096,
                    bid >> 5, bid & 31, smem_u32(sm), smem_u32(&mbar[0]));
        return;
    }

    // ---- attention: 2 batch rows ----
    const int tid = threadIdx.x, warp = tid >> 5, lane = tid & 31;
    const int b0 = (bid - 256) * 2;

    for (int i = tid; i < 2048; i += 256)
        sh[i >> 10][i & 1023] = a.h[(size_t)b0 * 1024 + i];
    __syncthreads();

    {
        const int row = warp >> 2, grp = warp & 3;
        const float4* t4 = (const float4*)sh[row];
#pragma unroll 1
        for (int j = 0; j < 16; ++j) {
            const int o = grp * 16 + j;
            const float4* w4 = (const float4*)(a.W + (size_t)o * a.wld);
            float acc = 0.f;
#pragma unroll
            for (int i = 0; i < 8; ++i) {
                float4 wv = w4[lane + (i << 5)];
                float4 tv = t4[lane + (i << 5)];
                acc = fmaf(wv.x, tv.x, fmaf(wv.y, tv.y,
                      fmaf(wv.z, tv.z, fmaf(wv.w, tv.w, acc))));
            }
#pragma unroll
            for (int off = 16; off > 0; off >>= 1)
                acc += __shfl_xor_sync(0xffffffffu, acc, off);
            if (lane == 0) slog[row][o] = acc + a.bias[o];
        }
    }
    __syncthreads();

    if (warp < 2) {
        float v0 = slog[warp][lane], v1 = slog[warp][lane + 32];
        float m = fmaxf(v0, v1);
#pragma unroll
        for (int off = 16; off > 0; off >>= 1)
            m = fmaxf(m, __shfl_xor_sync(0xffffffffu, m, off));
        float e0 = expf(v0 - m), e1 = expf(v1 - m);
        float s = e0 + e1;
#pragma unroll
        for (int off = 16; off > 0; off >>= 1)
            s += __shfl_xor_sync(0xffffffffu, s, off);
        float inv = 1.f / s;
        sw[warp][lane] = e0 * inv;
        sw[warp][lane + 32] = e1 * inv;
    }
    __syncthreads();

    const int row = tid >> 7, tl = tid & 127;
    const float4* e4 = (const float4*)(a.encW + (size_t)(b0 + row) * 65536);
    const float* wrow = sw[row];
#pragma unroll
    for (int rep = 0; rep < 2; ++rep) {
        const int d4 = tl + (rep << 7);
        float4 acc = make_float4(0.f, 0.f, 0.f, 0.f);
#pragma unroll 8
        for (int s = 0; s < SS; ++s) {
            float w = wrow[s];
            float4 ev = e4[s * 256 + d4];
            acc.x = fmaf(w, ev.x, acc.x);
            acc.y = fmaf(w, ev.y, acc.y);
            acc.z = fmaf(w, ev.z, acc.z);
            acc.w = fmaf(w, ev.w, acc.w);
        }
        *(float4*)&a.P[(size_t)(b0 + row) * 1024 + d4 * 4] = acc;
    }
}

// ---------------------------------------------------------------------------
// stepB: blocks 0..191 = gi GEMM; blocks 192..255 (t>=64) = early Wo blocks
// ---------------------------------------------------------------------------
struct StepBArgs {
    const char *grP, *WihP;
    const float* bih;
    float* gi;
    const char *HallP, *WoP;
    const float* bo;
    float* outseq;
    int t;
};

__global__ __launch_bounds__(256, 2) void stepB_kernel(StepBArgs a)
{
    extern __shared__ char sm[];
    __shared__ uint64_t mbar[2];
    const int bid = blockIdx.x;
    if (bid < 192) {
        gemm4_block(a.grP, a.WihP, a.bih, a.gi, 3072,
                    bid / 24, bid % 24, smem_u32(sm), smem_u32(&mbar[0]));
    } else {
        const int idx = (a.t - 64) * 64 + (bid - 192);
        gemm4_block(a.HallP, a.WoP, a.bo, a.outseq, 1024,
                    2 * (idx >> 3), idx & 7, smem_u32(sm), smem_u32(&mbar[0]));
    }
}

// ---------------------------------------------------------------------------
// gruin = relu(P + (t>0 ? U : bc)) -> packed split bf16
// ---------------------------------------------------------------------------
__global__ __launch_bounds__(256) void gruin_kernel(
    const float* __restrict__ P, const float* __restrict__ ghU,
    const float* __restrict__ bc, int t, char* __restrict__ grP)
{
    const int e = (blockIdx.x * 256 + threadIdx.x) * 2;
    const int m = e >> 10, d = e & 1023;
    float a0, a1;
    if (t > 0) {
        const float* u = ghU + (size_t)m * 4096 + 3072 + d;
        a0 = u[0]; a1 = u[1];
    } else { a0 = bc[d]; a1 = bc[d + 1]; }
    float v0 = fmaxf(P[e] + a0, 0.f);
    float v1 = fmaxf(P[e + 1] + a1, 0.f);
    __nv_bfloat162 hv, lv;
    split2(v0, hv.x, lv.x); split2(v1, hv.y, lv.y);
    const size_t off = pa_off(m >> 6, d >> 6, m & 63, (d & 63) * 2);
    *(__nv_bfloat162*)(grP + off) = hv;
    *(__nv_bfloat162*)(grP + off + 8192) = lv;
}

// ---------------------------------------------------------------------------
// GRU gates -> h (fp32), h packed, Hall packed
// ---------------------------------------------------------------------------
__global__ __launch_bounds__(256) void gate_kernel(
    const float* __restrict__ gi, const float* __restrict__ ghU,
    float* __restrict__ h, char* __restrict__ hP, char* __restrict__ HallP, int t)
{
    const int e = (blockIdx.x * 256 + threadIdx.x) * 2;
    const int m = e >> 10, d = e & 1023;
    float hn[2];
#pragma unroll
    for (int j = 0; j < 2; ++j) {
        const size_t b3 = (size_t)m * 3072 + d + j;
        const size_t b4 = (size_t)m * 4096 + d + j;
        float r = 1.f / (1.f + expf(-(gi[b3] + ghU[b4])));
        float z = 1.f / (1.f + expf(-(gi[b3 + 1024] + ghU[b4 + 1024])));
        float n = tanhf(gi[b3 + 2048] + r * ghU[b4 + 2048]);
        hn[j] = (1.f - z) * n + z * h[e + j];
    }
    *(float2*)&h[e] = make_float2(hn[0], hn[1]);
    __nv_bfloat162 hv, lv;
    split2(hn[0], hv.x, lv.x); split2(hn[1], hv.y, lv.y);
    const size_t off = pa_off(m >> 6, d >> 6, m & 63, (d & 63) * 2);
    *(__nv_bfloat162*)(hP + off) = hv;
    *(__nv_bfloat162*)(hP + off + 8192) = lv;
    const int M = m * 128 + t;
    const size_t hoff = pa_off(M >> 6, d >> 6, M & 63, (d & 63) * 2);
    *(__nv_bfloat162*)(HallP + hoff) = hv;
    *(__nv_bfloat162*)(HallP + hoff + 8192) = lv;
}

// ---------------------------------------------------------------------------
// Mega setup: split+pack everything, folds, biasG, init h. One launch.
// ---------------------------------------------------------------------------
struct SetupArgs {
    const float *Wih, *Whh, *Wo, *Wc, *enc, *Wa, *ba, *bo, *bc, *bhh, *hid;
    char *WihP, *WhhUP, *WoP, *WcBP, *encP, *hP;
    __nv_bfloat16 *WoT_hi, *WoT_lo, *Wc1_hi, *Wc1_lo;
    float *WaF, *baF, *biasG, *h;
};

__device__ __forceinline__ void pack_w_f32(const float* src, int ld, int i,
                                           char* dst, int row_base)
{
    const int n = i >> 10, k = i & 1023;
    const float v0 = src[(size_t)n * ld + k];
    const float v1 = src[(size_t)n * ld + k + 1];
    __nv_bfloat162 hv, lv;
    split2(v0, hv.x, lv.x); split2(v1, hv.y, lv.y);
    const int N = n + row_base;
    const size_t off = pw_off(N >> 7, k >> 6, N & 127, (k & 63) * 2);
    *(__nv_bfloat162*)(dst + off) = hv;
    *(__nv_bfloat162*)(dst + off + 16384) = lv;
}

#define MS_N0 6144    // pack Wih
#define MS_N1 6144    // pack Whh
#define MS_N2 2048    // pack Wo
#define MS_N3 1024    // WoT transpose+split
#define MS_N4 2048    // Wc1 linear split
#define MS_N5 2048    // pack WcB
#define MS_N6 65536   // pack enc (A layout)
#define MS_N7 64      // fold Wa
#define MS_N8 128     // fold bc -> biasG[3072:]
#define MS_N9 12      // bhh -> biasG[0:3072]
#define MS_N10 1024   // init h
#define MS_TOTAL (MS_N0+MS_N1+MS_N2+MS_N3+MS_N4+MS_N5+MS_N6+MS_N7+MS_N8+MS_N9+MS_N10)

__global__ __launch_bounds__(256) void mega_setup_kernel(SetupArgs a)
{
    __shared__ float sbuf[1088];
    int b = blockIdx.x;
    const int tid = threadIdx.x;

    if (b < MS_N0) { pack_w_f32(a.Wih, 1024, (b * 256 + tid) * 2, a.WihP, 0); return; }
    b -= MS_N0;
    if (b < MS_N1) { pack_w_f32(a.Whh, 1024, (b * 256 + tid) * 2, a.WhhUP, 0); return; }
    b -= MS_N1;
    if (b < MS_N2) { pack_w_f32(a.Wo, 1024, (b * 256 + tid) * 2, a.WoP, 0); return; }
    b -= MS_N2;
    if (b < MS_N3) {
        const int bx = (b & 31) * 32, by = (b >> 5) * 32;
        const int tx = tid & 31, ty = tid >> 5;
#pragma unroll
        for (int r = 0; r < 4; ++r)
            sbuf[(ty + 8 * r) * 33 + tx] = a.Wo[(size_t)(by + ty + 8 * r) * 1024 + bx + tx];
        __syncthreads();
#pragma unroll
        for (int r = 0; r < 4; ++r) {
            float v = sbuf[tx * 33 + ty + 8 * r];
            size_t o = (size_t)(bx + ty + 8 * r) * 1024 + by + tx;
            split2(v, a.WoT_hi[o], a.WoT_lo[o]);
        }
        return;
    }
    b -= MS_N3;
    if (b < MS_N4) {
        int i = (b * 256 + tid) * 2;
        int r = i >> 10, c = i & 1023;
        split2(a.Wc[(size_t)r * 2048 + c], a.Wc1_hi[i], a.Wc1_lo[i]);
        split2(a.Wc[(size_t)r * 2048 + c + 1], a.Wc1_hi[i + 1], a.Wc1_lo[i + 1]);
        return;
    }
    b -= MS_N4;
    if (b < MS_N5) { pack_w_f32(a.Wc + 1024, 2048, (b * 256 + tid) * 2, a.WcBP, 0); return; }
    b -= MS_N5;
    if (b < MS_N6) {
        const size_t i = ((size_t)b * 256 + tid) * 2;
        const int M = (int)(i >> 10), k = (int)(i & 1023);
        __nv_bfloat162 hv, lv;
        split2(a.enc[i], hv.x, lv.x);
        split2(a.enc[i + 1], hv.y, lv.y);
        const size_t off = pa_off(M >> 6, k >> 6, M & 63, (k & 63) * 2);
        *(__nv_bfloat162*)(a.encP + off) = hv;
        *(__nv_bfloat162*)(a.encP + off + 8192) = lv;
        return;
    }
    b -= MS_N6;
    if (b < MS_N7) {
        const int o = b;
        for (int i = tid; i < 1024; i += 256) sbuf[i] = a.Wa[(size_t)o * 2048 + i];
        __syncthreads();
        for (int j = tid; j < 1024; j += 256) {
            float acc = a.Wa[(size_t)o * 2048 + 1024 + j];
            for (int k = 0; k < 1024; ++k)
                acc = fmaf(sbuf[k], a.Wo[(size_t)k * 1024 + j], acc);
            a.WaF[(size_t)o * 1024 + j] = acc;
        }
        if (tid < 32) {
            float s = 0.f;
            for (int k = tid; k < 1024; k += 32) s += sbuf[k] * a.bo[k];
#pragma unroll
            for (int off = 16; off > 0; off >>= 1)
                s += __shfl_xor_sync(0xffffffffu, s, off);
            if (tid == 0) a.baF[o] = a.ba[o] + s;
        }
        return;
    }
    b -= MS_N7;
    if (b < MS_N8) {
        const int n = b * 8 + (tid >> 5);
        const int lane = tid & 31;
        float s = 0.f;
        for (int k = lane; k < 1024; k += 32) s += a.Wc[(size_t)n * 2048 + k] * a.bo[k];
#pragma unroll
        for (int off = 16; off > 0; off >>= 1)
            s += __shfl_xor_sync(0xffffffffu, s, off);
        if (lane == 0) a.biasG[3072 + n] = a.bc[n] + s;
        return;
    }
    b -= MS_N8;
    if (b < MS_N9) {
        int i = b * 256 + tid;
        a.biasG[i] = a.bhh[i];
        return;
    }
    b -= MS_N9;
    {
        int i = (b * 256 + tid) * 2;
        int m = i >> 10, d = i & 1023;
        float v0 = a.hid[i], v1 = a.hid[i + 1];
        *(float2*)&a.h[i] = make_float2(v0, v1);
        __nv_bfloat162 hv, lv;
        split2(v0, hv.x, lv.x); split2(v1, hv.y, lv.y);
        const size_t off = pa_off(m >> 6, d >> 6, m & 63, (d & 63) * 2);
        *(__nv_bfloat162*)(a.hP + off) = hv;
        *(__nv_bfloat162*)(a.hP + off + 8192) = lv;
    }
}

__global__ void copyf_kernel(const float* __restrict__ s, float* __restrict__ d, int n)
{
    int i = blockIdx.x * 256 + threadIdx.x;
    if (i < n) d[i] = s[i];
}

// ---------------------------------------------------------------------------
extern "C" void kernel_launch(void* const* d_in, const int* in_sizes, int n_in,
                              void* d_out, int out_size)
{
    const float* enc = (const float*)d_in[0];
    const float* hid = (const float*)d_in[1];
    const float* Wa  = (const float*)d_in[3];
    const float* ba  = (const float*)d_in[4];
    const float* Wc  = (const float*)d_in[5];
    const float* bc  = (const float*)d_in[6];
    const float* Wih = (const float*)d_in[7];
    const float* Whh = (const float*)d_in[8];
    const float* bih = (const float*)d_in[9];
    const float* bhh = (const float*)d_in[10];
    const float* Wo  = (const float*)d_in[11];
    const float* bo  = (const float*)d_in[12];

    float* outseq = (float*)d_out;
    float* outh   = outseq + (size_t)BB * TT * HH;

    __nv_bfloat16 *pWoT_hi, *pWoT_lo, *pWc1_hi, *pWc1_lo;
    char *pWihP, *pWhhUP, *pWoP, *pWcBP, *pencP, *pgrP, *phP, *pHallP;
    float *ph, *pgi, *pghU, *pzero, *pWaF, *pbaF, *pbiasG, *pencW, *pP;
    cudaGetSymbolAddress((void**)&pWoT_hi, g_WoT_hi); cudaGetSymbolAddress((void**)&pWoT_lo, g_WoT_lo);
    cudaGetSymbolAddress((void**)&pWc1_hi, g_Wc1_hi); cudaGetSymbolAddress((void**)&pWc1_lo, g_Wc1_lo);
    cudaGetSymbolAddress((void**)&pWihP, g_WihP);     cudaGetSymbolAddress((void**)&pWhhUP, g_WhhUP);
    cudaGetSymbolAddress((void**)&pWoP, g_WoP);       cudaGetSymbolAddress((void**)&pWcBP, g_WcBP);
    cudaGetSymbolAddress((void**)&pencP, g_encP);     cudaGetSymbolAddress((void**)&pgrP, g_grP);
    cudaGetSymbolAddress((void**)&phP, g_hP);         cudaGetSymbolAddress((void**)&pHallP, g_HallP);
    cudaGetSymbolAddress((void**)&ph, g_h);           cudaGetSymbolAddress((void**)&pgi, g_gi);
    cudaGetSymbolAddress((void**)&pghU, g_ghU);       cudaGetSymbolAddress((void**)&pzero, g_zero);
    cudaGetSymbolAddress((void**)&pWaF, g_WaF);       cudaGetSymbolAddress((void**)&pbaF, g_baF);
    cudaGetSymbolAddress((void**)&pbiasG, g_biasGhU);
    cudaGetSymbolAddress((void**)&pencW, g_encW);     cudaGetSymbolAddress((void**)&pP, g_P);

    cudaFuncSetAttribute(gemm_std_kernel, cudaFuncAttributeMaxDynamicSharedMemorySize, ENG_SMEM);
    cudaFuncSetAttribute(gemm4_kernel, cudaFuncAttributeMaxDynamicSharedMemorySize, V4_SMEM);
    cudaFuncSetAttribute(stepA_kernel, cudaFuncAttributeMaxDynamicSharedMemorySize, V4_SMEM);
    cudaFuncSetAttribute(stepB_kernel, cudaFuncAttributeMaxDynamicSharedMemorySize, V4_SMEM);

    // ---- launch 1: mega setup ----
    {
        SetupArgs s{};
        s.Wih = Wih; s.Whh = Whh; s.Wo = Wo; s.Wc = Wc; s.enc = enc;
        s.Wa = Wa; s.ba = ba; s.bo = bo; s.bc = bc; s.bhh = bhh; s.hid = hid;
        s.WihP = pWihP; s.WhhUP = pWhhUP; s.WoP = pWoP; s.WcBP = pWcBP;
        s.encP = pencP; s.hP = phP;
        s.WoT_hi = pWoT_hi; s.WoT_lo = pWoT_lo; s.Wc1_hi = pWc1_hi; s.Wc1_lo = pWc1_lo;
        s.WaF = pWaF; s.baF = pbaF; s.biasG = pbiasG; s.h = ph;
        mega_setup_kernel<<<MS_TOTAL, 256>>>(s);
    }
    // ---- launch 2: encW = enc @ WcB^T (v4, M=32768) ----
    gemm4_kernel<<<dim3(8, 512), 256, V4_SMEM>>>(pencP, pWcBP, pzero, pencW, 1024, 1, 0);
    // ---- launch 3: WcF = Wc1 @ Wo (v3, mode 3: direct pack into WhhUP rows 3072+) ----
    {
        GProb p = { pWc1_hi, pWc1_lo, 1024, pWoT_hi, pWoT_lo, 1024, 1024,
                    pzero, nullptr, 0, (__nv_bfloat16*)pWhhUP, nullptr, 3072, 3 };
        gemm_std_kernel<<<dim3(8, 16), 256, ENG_SMEM>>>(p);
    }

    // ---- decode loop (launch #4 = stepA t=0 -> ncu capture target) ----
    for (int t = 0; t < TT; ++t) {
        {
            StepAArgs a{};
            a.hP = phP; a.WhhUP = pWhhUP; a.biasG = pbiasG; a.ghU = pghU;
            a.h = ph; a.encW = pencW;
            a.W = (t == 0) ? (Wa + 1024) : pWaF;
            a.wld = (t == 0) ? 2048 : 1024;
            a.bias = (t == 0) ? ba : pbaF;
            a.P = pP;
            stepA_kernel<<<512, 256, V4_SMEM>>>(a);
        }
        gruin_kernel<<<BB * HH / 512, 256>>>(pP, pghU, bc, t, pgrP);
        {
            StepBArgs a{};
            a.grP = pgrP; a.WihP = pWihP; a.bih = bih; a.gi = pgi;
            a.HallP = pHallP; a.WoP = pWoP; a.bo = bo; a.outseq = outseq;
            a.t = t;
            stepB_kernel<<<(t >= 64) ? 256 : 192, 256, V4_SMEM>>>(a);
        }
        gate_kernel<<<BB * HH / 512, 256>>>(pgi, pghU, ph, phP, pHallP, t);
    }

    // ---- tail: odd Hall mtiles of outseq = Hall @ Wo^T + bo ----
    gemm4_kernel<<<dim3(8, 512), 256, V4_SMEM>>>(pHallP, pWoP, bo, outseq, 1024, 2, 1);

    if (out_size >= BB * TT * HH + BB * HH) {
        copyf_kernel<<<BB * HH / 256, 256>>>(ph, outh, BB * HH);
    }
}

// round 12
// speedup vs baseline: 1.0942x; 1.0942x over previous
#include <cuda_runtime.h>
#include <cuda_bf16.h>
#include <cuda_fp16.h>
#include <cstdint>

#define BB 512
#define HH 1024
#define SS 64
#define TT 128

// ---------------------------------------------------------------------------
// Device-global scratch (allocation-free)
// ---------------------------------------------------------------------------
__device__ __align__(256) __nv_bfloat16 g_WoT_hi[1024 * 1024], g_WoT_lo[1024 * 1024];
__device__ __align__(256) __nv_bfloat16 g_Wc1_hi[1024 * 1024], g_Wc1_lo[1024 * 1024];
// folded attention weights
__device__ __align__(256) float g_WaF[64 * 1024];
__device__ __align__(256) float g_baF[64];
__device__ __align__(256) float g_biasGhU[4096];
// packed v4 slabs:  W slab (ntile,ks) -> 32768 B [hi|lo], rows 128 x cols 64
//                   A slab (mtile,ks) -> 16384 B [hi|lo], rows 64 x cols 64
__device__ __align__(256) char g_WihP[24 * 16 * 32768];
__device__ __align__(256) char g_WhhUP[32 * 16 * 32768];     // [Whh(3072) | WcF(1024)]
__device__ __align__(256) char g_WoP[8 * 16 * 32768];
__device__ __align__(256) char g_WcBP[8 * 16 * 32768];
__device__ __align__(256) char g_encP[(size_t)512 * 16 * 16384];
__device__ __align__(256) char g_grP[8 * 16 * 16384];
__device__ __align__(256) char g_hP[8 * 16 * 16384];
__device__ __align__(256) char g_HallP[(size_t)1024 * 16 * 16384];
// fp16 encW = enc @ WcB^T  (attention-apply operand; fp32 accum at use)
__device__ __align__(256) __half g_encWh[(size_t)32768 * 1024];
// fp32 activations
__device__ __align__(256) float g_P[512 * 1024];
__device__ __align__(256) float g_h[512 * 1024];
__device__ __align__(256) float g_ghU[512 * 4096];           // [gh(3072) | U(1024)]
__device__ __align__(256) float g_gi[512 * 3072];
__device__ __align__(256) float g_zero[4096];

// ---------------------------------------------------------------------------
// Helpers
// ---------------------------------------------------------------------------
__device__ __forceinline__ void split2(float v, __nv_bfloat16& hi, __nv_bfloat16& lo) {
    hi = __float2bfloat16(v);
    lo = __float2bfloat16(v - __bfloat162float(hi));
}

__device__ __host__ __forceinline__ uint32_t swz(uint32_t off) {
    return off ^ ((off >> 3) & 0x70);
}
__device__ __forceinline__ size_t pa_off(int mt, int ks, int row, int col2) {
    return (size_t)(mt * 16 + ks) * 16384 + swz((uint32_t)(row * 128 + col2));
}
__device__ __forceinline__ size_t pw_off(int nt, int ks, int row, int col2) {
    return (size_t)(nt * 16 + ks) * 32768 + swz((uint32_t)(row * 128 + col2));
}

__device__ __forceinline__ uint32_t smem_u32(const void* p) {
    uint32_t a;
    asm("{ .reg .u64 t; cvta.to.shared.u64 t, %1; cvt.u32.u64 %0, t; }" : "=r"(a) : "l"(p));
    return a;
}

__device__ __forceinline__ void ldsm_x4(uint32_t* r, uint32_t addr) {
    asm volatile("ldmatrix.sync.aligned.m8n8.x4.shared.b16 {%0,%1,%2,%3}, [%4];\n"
                 : "=r"(r[0]), "=r"(r[1]), "=r"(r[2]), "=r"(r[3]) : "r"(addr));
}

__device__ __forceinline__ void mma_bf16(float* c, const uint32_t* a, const uint32_t* b) {
    asm volatile(
        "mma.sync.aligned.m16n8k16.row.col.f32.bf16.bf16.f32 "
        "{%0,%1,%2,%3}, {%4,%5,%6,%7}, {%8,%9}, {%0,%1,%2,%3};\n"
        : "+f"(c[0]), "+f"(c[1]), "+f"(c[2]), "+f"(c[3])
        : "r"(a[0]), "r"(a[1]), "r"(a[2]), "r"(a[3]), "r"(b[0]), "r"(b[1]));
}

__device__ __forceinline__ void cp16a(uint32_t dst, const void* src) {
    asm volatile("cp.async.cg.shared.global [%0], [%1], 16;\n" :: "r"(dst), "l"(src));
}
#define CP_COMMIT() asm volatile("cp.async.commit_group;\n" ::: "memory")
#define CP_WAIT1()  asm volatile("cp.async.wait_group 1;\n" ::: "memory")

#define MBAR_INIT(mb, c) asm volatile("mbarrier.init.shared.b64 [%0], %1;" :: "r"((uint32_t)(mb)), "r"((uint32_t)(c)) : "memory")
#define EXPECT_TX(mb, n) asm volatile("mbarrier.arrive.expect_tx.shared.b64 _, [%0], %1;" :: "r"((uint32_t)(mb)), "r"((uint32_t)(n)) : "memory")
#define BULK_CP(dst, src, n, mb) \
    asm volatile("cp.async.bulk.shared::cluster.global.mbarrier::complete_tx::bytes [%0], [%1], %2, [%3];" \
        :: "r"((uint32_t)(dst)), "l"(src), "r"((uint32_t)(n)), "r"((uint32_t)(mb)) : "memory")

#define MBAR_WAIT(mb, par) do { \
    uint32_t _m = (uint32_t)(mb); uint32_t _p = (uint32_t)(par); uint32_t _d; \
    asm volatile("{\n\t.reg .pred p;\n\t" \
        "mbarrier.try_wait.parity.acquire.cta.shared::cta.b64 p, [%1], %2;\n\t" \
        "selp.b32 %0, 1, 0, p;\n\t}" : "=r"(_d) : "r"(_m), "r"(_p) : "memory"); \
    if (!_d) { \
        asm volatile("{\n\t.reg .pred P1;\n\t" \
            "WL_%=:\n\t" \
            "mbarrier.try_wait.parity.acquire.cta.shared::cta.b64 P1, [%0], %1, 0x989680;\n\t" \
            "@P1 bra.uni WD_%=;\n\t" \
            "bra.uni WL_%=;\n\t" \
            "WD_%=:\n\t}" :: "r"(_m), "r"(_p) : "memory"); \
    } \
} while (0)

// ---------------------------------------------------------------------------
// Engine v3 (cp.async 16B path) — setup WcF GEMM only.
// mode 3: split output written DIRECTLY into packed W slab (Chi=slab, ldch=row base)
// ---------------------------------------------------------------------------
struct GProb {
    const __nv_bfloat16 *Ahi, *Alo; int lda;
    const __nv_bfloat16 *Whi, *Wlo; int ldw;
    int K;
    const float* bias;
    float* Cf; int ldc;
    __nv_bfloat16 *Chi, *Clo; int ldch;
    int mode;
};

#define ENG_ALO 9216u
#define ENG_WHI 18432u
#define ENG_WLO 36864u
#define ENG_STAGE 55296u
#define ENG_SMEM 110592

__global__ __launch_bounds__(256, 2) void gemm_std_kernel(GProb p)
{
    extern __shared__ char sm[];
    const uint32_t smbase = smem_u32(sm);
    const int tid = threadIdx.x, warp = tid >> 5, lane = tid & 31;
    const int m0 = blockIdx.y * 64, n0 = blockIdx.x * 128;
    const int S = p.K >> 6;
    const int wm = warp >> 2, wn = warp & 3;
    const int lr = tid >> 1;
    const int lc = (tid & 1) * 4;

    float acc[2][4][4];
#pragma unroll
    for (int mi = 0; mi < 2; ++mi)
#pragma unroll
        for (int nf = 0; nf < 4; ++nf)
#pragma unroll
            for (int q = 0; q < 4; ++q) acc[mi][nf][q] = 0.f;

    const __nv_bfloat16* abase = (lr < 64)
        ? p.Ahi + (size_t)(m0 + lr) * p.lda
        : p.Alo + (size_t)(m0 + lr - 64) * p.lda;
    const __nv_bfloat16* w1base = p.Whi + (size_t)(n0 + lr) * p.ldw;
    const __nv_bfloat16* w2base = p.Wlo + (size_t)(n0 + lr) * p.ldw;
    const uint32_t rowb = (uint32_t)lr * 144 + (uint32_t)lc * 16;

    auto load_stage = [&](int s) {
        const int k0 = (s << 6) + lc * 8;
        const uint32_t sb = smbase + (uint32_t)(s & 1) * ENG_STAGE;
#pragma unroll
        for (int c = 0; c < 4; ++c) cp16a(sb + rowb + c * 16, abase + k0 + c * 8);
#pragma unroll
        for (int c = 0; c < 4; ++c) cp16a(sb + ENG_WHI + rowb + c * 16, w1base + k0 + c * 8);
#pragma unroll
        for (int c = 0; c < 4; ++c) cp16a(sb + ENG_WLO + rowb + c * 16, w2base + k0 + c * 8);
    };

    load_stage(0); CP_COMMIT();
    load_stage(1); CP_COMMIT();

    const int arow = wm * 32 + (lane & 15);
    const int acolb = (lane >> 4) << 3;
    const int g = lane >> 3;
    const int brow = wn * 32 + ((g >> 1) << 3) + (lane & 7);
    const int bcolb = (g & 1) << 3;

    for (int s = 0; s < S; ++s) {
        CP_WAIT1();
        __syncthreads();
        const uint32_t sb = smbase + (uint32_t)(s & 1) * ENG_STAGE;
#pragma unroll
        for (int kk = 0; kk < 4; ++kk) {
            const int acol = kk * 16 + acolb;
            uint32_t ahi[2][4], alo[2][4];
#pragma unroll
            for (int mi = 0; mi < 2; ++mi) {
                const uint32_t off = (uint32_t)((arow + mi * 16) * 144 + acol * 2);
                ldsm_x4(ahi[mi], sb + off);
                ldsm_x4(alo[mi], sb + ENG_ALO + off);
            }
            const int bcol = kk * 16 + bcolb;
            uint32_t bhi[4][2], blo[4][2];
#pragma unroll
            for (int nh = 0; nh < 2; ++nh) {
                uint32_t r[4];
                const uint32_t off = (uint32_t)((brow + nh * 16) * 144 + bcol * 2);
                ldsm_x4(r, sb + ENG_WHI + off);
                bhi[nh * 2 + 0][0] = r[0]; bhi[nh * 2 + 0][1] = r[1];
                bhi[nh * 2 + 1][0] = r[2]; bhi[nh * 2 + 1][1] = r[3];
                ldsm_x4(r, sb + ENG_WLO + off);
                blo[nh * 2 + 0][0] = r[0]; blo[nh * 2 + 0][1] = r[1];
                blo[nh * 2 + 1][0] = r[2]; blo[nh * 2 + 1][1] = r[3];
            }
#pragma unroll
            for (int mi = 0; mi < 2; ++mi)
#pragma unroll
                for (int nf = 0; nf < 4; ++nf)
                    mma_bf16(acc[mi][nf], ahi[mi], bhi[nf]);
#pragma unroll
            for (int mi = 0; mi < 2; ++mi)
#pragma unroll
                for (int nf = 0; nf < 4; ++nf)
                    mma_bf16(acc[mi][nf], ahi[mi], blo[nf]);
#pragma unroll
            for (int mi = 0; mi < 2; ++mi)
#pragma unroll
                for (int nf = 0; nf < 4; ++nf)
                    mma_bf16(acc[mi][nf], alo[mi], bhi[nf]);
        }
        __syncthreads();
        if (s + 2 < S) load_stage(s + 2);
        CP_COMMIT();
    }

    const int row0 = m0 + wm * 32 + (lane >> 2);
    const int col0 = n0 + wn * 32 + ((lane & 3) << 1);
#pragma unroll
    for (int mi = 0; mi < 2; ++mi) {
#pragma unroll
        for (int nf = 0; nf < 4; ++nf) {
            const int col = col0 + nf * 8;
            const float b0 = p.bias[col], b1 = p.bias[col + 1];
#pragma unroll
            for (int half = 0; half < 2; ++half) {
                const int row = row0 + mi * 16 + half * 8;
                float v0 = acc[mi][nf][half * 2 + 0] + b0;
                float v1 = acc[mi][nf][half * 2 + 1] + b1;
                if (p.mode == 0) {
                    *(float2*)&p.Cf[(size_t)row * p.ldc + col] = make_float2(v0, v1);
                } else if (p.mode == 3) {
                    __nv_bfloat162 hv, lv;
                    split2(v0, hv.x, lv.x); split2(v1, hv.y, lv.y);
                    char* dst = (char*)p.Chi;
                    const int N = p.ldch + row;
                    const size_t off = pw_off(N >> 7, col >> 6, N & 127, (col & 63) * 2);
                    *(__nv_bfloat162*)(dst + off) = hv;
                    *(__nv_bfloat162*)(dst + off + 16384) = lv;
                }
            }
        }
    }
}

// ---------------------------------------------------------------------------
// v4 GEMM block body: packed operands, cp.async.bulk, K=1024 (16 stages).
// outmode 0: fp32 out; 1: fp16 out (Cf reinterpreted as __half*).
// ---------------------------------------------------------------------------
#define V4_SMEM 98304

__device__ __forceinline__ void gemm4_block(
    const char* __restrict__ Apack, const char* __restrict__ Wpack,
    const float* __restrict__ bias, float* __restrict__ Cf, int ldc,
    int mtile, int ntile, uint32_t sb0, uint32_t mbb, int outmode)
{
    const int tid = threadIdx.x, warp = tid >> 5, lane = tid & 31;
    const char* Ab = Apack + (size_t)mtile * 16 * 16384;
    const char* Wb = Wpack + (size_t)ntile * 16 * 32768;
    const uint32_t mb[2] = { mbb, mbb + 8 };

    if (tid == 0) { MBAR_INIT(mb[0], 1); MBAR_INIT(mb[1], 1); }
    __syncthreads();

    auto issue = [&](int s) {
        const uint32_t dst = sb0 + (uint32_t)(s & 1) * 49152u;
        EXPECT_TX(mb[s & 1], 49152u);
        BULK_CP(dst, Ab + (size_t)s * 16384, 16384u, mb[s & 1]);
        BULK_CP(dst + 16384u, Wb + (size_t)s * 32768, 32768u, mb[s & 1]);
    };
    if (tid == 0) { issue(0); issue(1); }

    const int wm = warp >> 2, wn = warp & 3;
    const int arow = wm * 32 + (lane & 15);
    const int acolb = (lane >> 4) << 3;
    const int g = lane >> 3;
    const int brow = wn * 32 + ((g >> 1) << 3) + (lane & 7);
    const int bcolb = (g & 1) << 3;

    float acc[2][4][4];
#pragma unroll
    for (int mi = 0; mi < 2; ++mi)
#pragma unroll
        for (int nf = 0; nf < 4; ++nf)
#pragma unroll
            for (int q = 0; q < 4; ++q) acc[mi][nf][q] = 0.f;

    for (int s = 0; s < 16; ++s) {
        const int b = s & 1;
        MBAR_WAIT(mb[b], (s >> 1) & 1);
        const uint32_t sa = sb0 + (uint32_t)b * 49152u;
        const uint32_t sw = sa + 16384u;
#pragma unroll
        for (int kk = 0; kk < 4; ++kk) {
            const int acol = kk * 16 + acolb;
            uint32_t ahi[2][4], alo[2][4];
#pragma unroll
            for (int mi = 0; mi < 2; ++mi) {
                const uint32_t off = swz((uint32_t)((arow + mi * 16) * 128 + acol * 2));
                ldsm_x4(ahi[mi], sa + off);
                ldsm_x4(alo[mi], sa + 8192u + off);
            }
            const int bcol = kk * 16 + bcolb;
            uint32_t bhi[4][2], blo[4][2];
#pragma unroll
            for (int nh = 0; nh < 2; ++nh) {
                uint32_t r[4];
                const uint32_t off = swz((uint32_t)((brow + nh * 16) * 128 + bcol * 2));
                ldsm_x4(r, sw + off);
                bhi[nh * 2 + 0][0] = r[0]; bhi[nh * 2 + 0][1] = r[1];
                bhi[nh * 2 + 1][0] = r[2]; bhi[nh * 2 + 1][1] = r[3];
                ldsm_x4(r, sw + 16384u + off);
                blo[nh * 2 + 0][0] = r[0]; blo[nh * 2 + 0][1] = r[1];
                blo[nh * 2 + 1][0] = r[2]; blo[nh * 2 + 1][1] = r[3];
            }
#pragma unroll
            for (int mi = 0; mi < 2; ++mi)
#pragma unroll
                for (int nf = 0; nf < 4; ++nf)
                    mma_bf16(acc[mi][nf], ahi[mi], bhi[nf]);
#pragma unroll
            for (int mi = 0; mi < 2; ++mi)
#pragma unroll
                for (int nf = 0; nf < 4; ++nf)
                    mma_bf16(acc[mi][nf], ahi[mi], blo[nf]);
#pragma unroll
            for (int mi = 0; mi < 2; ++mi)
#pragma unroll
                for (int nf = 0; nf < 4; ++nf)
                    mma_bf16(acc[mi][nf], alo[mi], bhi[nf]);
        }
        __syncthreads();
        if (tid == 0 && s + 2 < 16) issue(s + 2);
    }

    const int row0 = mtile * 64 + wm * 32 + (lane >> 2);
    const int col0 = ntile * 128 + wn * 32 + ((lane & 3) << 1);
#pragma unroll
    for (int mi = 0; mi < 2; ++mi) {
#pragma unroll
        for (int nf = 0; nf < 4; ++nf) {
            const int col = col0 + nf * 8;
            const float b0 = bias[col], b1 = bias[col + 1];
#pragma unroll
            for (int half = 0; half < 2; ++half) {
                const int row = row0 + mi * 16 + half * 8;
                float v0 = acc[mi][nf][half * 2 + 0] + b0;
                float v1 = acc[mi][nf][half * 2 + 1] + b1;
                if (outmode == 0) {
                    *(float2*)&Cf[(size_t)row * ldc + col] = make_float2(v0, v1);
                } else {
                    __half2 hv = __floats2half2_rn(v0, v1);
                    *(__half2*)&((__half*)Cf)[(size_t)row * ldc + col] = hv;
                }
            }
        }
    }
}

// generic v4 launch wrapper; mtile = blockIdx.y * mscale + mbase
__global__ __launch_bounds__(256, 2) void gemm4_kernel(
    const char* __restrict__ Apack, const char* __restrict__ Wpack,
    const float* __restrict__ bias, float* __restrict__ Cf, int ldc,
    int mscale, int mbase, int outmode)
{
    extern __shared__ char sm[];
    __shared__ uint64_t mbar[2];
    gemm4_block(Apack, Wpack, bias, Cf, ldc,
                blockIdx.y * mscale + mbase, blockIdx.x,
                smem_u32(sm), smem_u32(&mbar[0]), outmode);
}

// ---------------------------------------------------------------------------
// stepA: 768 blocks, interleaved. bid%3==0 -> ghU GEMM tile (bid/3 of 256);
// else attention row b = (bid/3)*2 + (bid%3 - 1)  (512 rows).
// Attention: 1 batch row / block, 256 threads, fp16 encW, fp32 accum.
// ---------------------------------------------------------------------------
struct StepAArgs {
    const char *hP, *WhhUP;
    const float* biasG;
    float* ghU;
    const float *h;
    const __half* encW;
    const float *W, *bias;
    int wld;
    float* P;
};

__global__ __launch_bounds__(256, 2) void stepA_kernel(StepAArgs a)
{
    extern __shared__ char sm[];
    __shared__ uint64_t mbar[2];
    __shared__ float sh[1024];
    __shared__ float slog[64];
    __shared__ float sw[64];

    const int bid = blockIdx.x;
    const int g3 = bid / 3, r3 = bid - g3 * 3;
    if (r3 == 0) {
        gemm4_block(a.hP, a.WhhUP, a.biasG, a.ghU, 4096,
                    g3 >> 5, g3 & 31, smem_u32(sm), smem_u32(&mbar[0]), 0);
        return;
    }

    // ---- attention: one batch row ----
    const int tid = threadIdx.x, warp = tid >> 5, lane = tid & 31;
    const int b = g3 * 2 + (r3 - 1);

    *(float4*)&sh[tid * 4] = *(const float4*)&a.h[(size_t)b * 1024 + tid * 4];
    __syncthreads();

#pragma unroll 1
    for (int j = 0; j < 8; ++j) {
        const int o = warp * 8 + j;
        const float4* w4 = (const float4*)(a.W + (size_t)o * a.wld);
        const float4* t4 = (const float4*)sh;
        float acc = 0.f;
#pragma unroll
        for (int i = 0; i < 8; ++i) {
            float4 wv = w4[lane + (i << 5)];
            float4 tv = t4[lane + (i << 5)];
            acc = fmaf(wv.x, tv.x, fmaf(wv.y, tv.y,
                  fmaf(wv.z, tv.z, fmaf(wv.w, tv.w, acc))));
        }
#pragma unroll
        for (int off = 16; off > 0; off >>= 1)
            acc += __shfl_xor_sync(0xffffffffu, acc, off);
        if (lane == 0) slog[o] = acc + a.bias[o];
    }
    __syncthreads();

    if (warp == 0) {
        float v0 = slog[lane], v1 = slog[lane + 32];
        float m = fmaxf(v0, v1);
#pragma unroll
        for (int off = 16; off > 0; off >>= 1)
            m = fmaxf(m, __shfl_xor_sync(0xffffffffu, m, off));
        float e0 = expf(v0 - m), e1 = expf(v1 - m);
        float s = e0 + e1;
#pragma unroll
        for (int off = 16; off > 0; off >>= 1)
            s += __shfl_xor_sync(0xffffffffu, s, off);
        float inv = 1.f / s;
        sw[lane] = e0 * inv;
        sw[lane + 32] = e1 * inv;
    }
    __syncthreads();

    // P[b, 4t..4t+4) = sum_s w[s] * encW[b,s,4t..4t+4)   (fp16 loads, fp32 accum)
    const uint2* e2 = (const uint2*)(a.encW + (size_t)b * 65536) + tid;
    float4 acc = make_float4(0.f, 0.f, 0.f, 0.f);
#pragma unroll 8
    for (int s = 0; s < SS; ++s) {
        float w = sw[s];
        uint2 ev = e2[s * 256];
        __half2 h01 = *(__half2*)&ev.x;
        __half2 h23 = *(__half2*)&ev.y;
        float2 f01 = __half22float2(h01);
        float2 f23 = __half22float2(h23);
        acc.x = fmaf(w, f01.x, acc.x);
        acc.y = fmaf(w, f01.y, acc.y);
        acc.z = fmaf(w, f23.x, acc.z);
        acc.w = fmaf(w, f23.y, acc.w);
    }
    *(float4*)&a.P[(size_t)b * 1024 + tid * 4] = acc;
}

// ---------------------------------------------------------------------------
// stepB: blocks 0..191 = gi GEMM; blocks 192..255 (t>=64) = early Wo blocks
// ---------------------------------------------------------------------------
struct StepBArgs {
    const char *grP, *WihP;
    const float* bih;
    float* gi;
    const char *HallP, *WoP;
    const float* bo;
    float* outseq;
    int t;
};

__global__ __launch_bounds__(256, 2) void stepB_kernel(StepBArgs a)
{
    extern __shared__ char sm[];
    __shared__ uint64_t mbar[2];
    const int bid = blockIdx.x;
    if (bid < 192) {
        gemm4_block(a.grP, a.WihP, a.bih, a.gi, 3072,
                    bid / 24, bid % 24, smem_u32(sm), smem_u32(&mbar[0]), 0);
    } else {
        const int idx = (a.t - 64) * 64 + (bid - 192);
        gemm4_block(a.HallP, a.WoP, a.bo, a.outseq, 1024,
                    2 * (idx >> 3), idx & 7, smem_u32(sm), smem_u32(&mbar[0]), 0);
    }
}

// ---------------------------------------------------------------------------
// gruin = relu(P + (t>0 ? U : bc)) -> packed split bf16
// ---------------------------------------------------------------------------
__global__ __launch_bounds__(256) void gruin_kernel(
    const float* __restrict__ P, const float* __restrict__ ghU,
    const float* __restrict__ bc, int t, char* __restrict__ grP)
{
    const int e = (blockIdx.x * 256 + threadIdx.x) * 2;
    const int m = e >> 10, d = e & 1023;
    float a0, a1;
    if (t > 0) {
        const float* u = ghU + (size_t)m * 4096 + 3072 + d;
        a0 = u[0]; a1 = u[1];
    } else { a0 = bc[d]; a1 = bc[d + 1]; }
    float v0 = fmaxf(P[e] + a0, 0.f);
    float v1 = fmaxf(P[e + 1] + a1, 0.f);
    __nv_bfloat162 hv, lv;
    split2(v0, hv.x, lv.x); split2(v1, hv.y, lv.y);
    const size_t off = pa_off(m >> 6, d >> 6, m & 63, (d & 63) * 2);
    *(__nv_bfloat162*)(grP + off) = hv;
    *(__nv_bfloat162*)(grP + off + 8192) = lv;
}

// ---------------------------------------------------------------------------
// GRU gates -> h (fp32), h packed, Hall packed
// ---------------------------------------------------------------------------
__global__ __launch_bounds__(256) void gate_kernel(
    const float* __restrict__ gi, const float* __restrict__ ghU,
    float* __restrict__ h, char* __restrict__ hP, char* __restrict__ HallP, int t)
{
    const int e = (blockIdx.x * 256 + threadIdx.x) * 2;
    const int m = e >> 10, d = e & 1023;
    float hn[2];
#pragma unroll
    for (int j = 0; j < 2; ++j) {
        const size_t b3 = (size_t)m * 3072 + d + j;
        const size_t b4 = (size_t)m * 4096 + d + j;
        float r = 1.f / (1.f + expf(-(gi[b3] + ghU[b4])));
        float z = 1.f / (1.f + expf(-(gi[b3 + 1024] + ghU[b4 + 1024])));
        float n = tanhf(gi[b3 + 2048] + r * ghU[b4 + 2048]);
        hn[j] = (1.f - z) * n + z * h[e + j];
    }
    *(float2*)&h[e] = make_float2(hn[0], hn[1]);
    __nv_bfloat162 hv, lv;
    split2(hn[0], hv.x, lv.x); split2(hn[1], hv.y, lv.y);
    const size_t off = pa_off(m >> 6, d >> 6, m & 63, (d & 63) * 2);
    *(__nv_bfloat162*)(hP + off) = hv;
    *(__nv_bfloat162*)(hP + off + 8192) = lv;
    const int M = m * 128 + t;
    const size_t hoff = pa_off(M >> 6, d >> 6, M & 63, (d & 63) * 2);
    *(__nv_bfloat162*)(HallP + hoff) = hv;
    *(__nv_bfloat162*)(HallP + hoff + 8192) = lv;
}

// ---------------------------------------------------------------------------
// Mega setup: split+pack everything, folds, biasG, init h. One launch.
// ---------------------------------------------------------------------------
struct SetupArgs {
    const float *Wih, *Whh, *Wo, *Wc, *enc, *Wa, *ba, *bo, *bc, *bhh, *hid;
    char *WihP, *WhhUP, *WoP, *WcBP, *encP, *hP;
    __nv_bfloat16 *WoT_hi, *WoT_lo, *Wc1_hi, *Wc1_lo;
    float *WaF, *baF, *biasG, *h;
};

__device__ __forceinline__ void pack_w_f32(const float* src, int ld, int i,
                                           char* dst, int row_base)
{
    const int n = i >> 10, k = i & 1023;
    const float v0 = src[(size_t)n * ld + k];
    const float v1 = src[(size_t)n * ld + k + 1];
    __nv_bfloat162 hv, lv;
    split2(v0, hv.x, lv.x); split2(v1, hv.y, lv.y);
    const int N = n + row_base;
    const size_t off = pw_off(N >> 7, k >> 6, N & 127, (k & 63) * 2);
    *(__nv_bfloat162*)(dst + off) = hv;
    *(__nv_bfloat162*)(dst + off + 16384) = lv;
}

#define MS_N0 6144    // pack Wih
#define MS_N1 6144    // pack Whh
#define MS_N2 2048    // pack Wo
#define MS_N3 1024    // WoT transpose+split
#define MS_N4 2048    // Wc1 linear split
#define MS_N5 2048    // pack WcB
#define MS_N6 65536   // pack enc (A layout)
#define MS_N7 64      // fold Wa
#define MS_N8 128     // fold bc -> biasG[3072:]
#define MS_N9 12      // bhh -> biasG[0:3072]
#define MS_N10 1024   // init h
#define MS_TOTAL (MS_N0+MS_N1+MS_N2+MS_N3+MS_N4+MS_N5+MS_N6+MS_N7+MS_N8+MS_N9+MS_N10)

__global__ __launch_bounds__(256) void mega_setup_kernel(SetupArgs a)
{
    __shared__ float sbuf[1088];
    int b = blockIdx.x;
    const int tid = threadIdx.x;

    if (b < MS_N0) { pack_w_f32(a.Wih, 1024, (b * 256 + tid) * 2, a.WihP, 0); return; }
    b -= MS_N0;
    if (b < MS_N1) { pack_w_f32(a.Whh, 1024, (b * 256 + tid) * 2, a.WhhUP, 0); return; }
    b -= MS_N1;
    if (b < MS_N2) { pack_w_f32(a.Wo, 1024, (b * 256 + tid) * 2, a.WoP, 0); return; }
    b -= MS_N2;
    if (b < MS_N3) {
        const int bx = (b & 31) * 32, by = (b >> 5) * 32;
        const int tx = tid & 31, ty = tid >> 5;
#pragma unroll
        for (int r = 0; r < 4; ++r)
            sbuf[(ty + 8 * r) * 33 + tx] = a.Wo[(size_t)(by + ty + 8 * r) * 1024 + bx + tx];
        __syncthreads();
#pragma unroll
        for (int r = 0; r < 4; ++r) {
            float v = sbuf[tx * 33 + ty + 8 * r];
            size_t o = (size_t)(bx + ty + 8 * r) * 1024 + by + tx;
            split2(v, a.WoT_hi[o], a.WoT_lo[o]);
        }
        return;
    }
    b -= MS_N3;
    if (b < MS_N4) {
        int i = (b * 256 + tid) * 2;
        int r = i >> 10, c = i & 1023;
        split2(a.Wc[(size_t)r * 2048 + c], a.Wc1_hi[i], a.Wc1_lo[i]);
        split2(a.Wc[(size_t)r * 2048 + c + 1], a.Wc1_hi[i + 1], a.Wc1_lo[i + 1]);
        return;
    }
    b -= MS_N4;
    if (b < MS_N5) { pack_w_f32(a.Wc + 1024, 2048, (b * 256 + tid) * 2, a.WcBP, 0); return; }
    b -= MS_N5;
    if (b < MS_N6) {
        const size_t i = ((size_t)b * 256 + tid) * 2;
        const int M = (int)(i >> 10), k = (int)(i & 1023);
        __nv_bfloat162 hv, lv;
        split2(a.enc[i], hv.x, lv.x);
        split2(a.enc[i + 1], hv.y, lv.y);
        const size_t off = pa_off(M >> 6, k >> 6, M & 63, (k & 63) * 2);
        *(__nv_bfloat162*)(a.encP + off) = hv;
        *(__nv_bfloat162*)(a.encP + off + 8192) = lv;
        return;
    }
    b -= MS_N6;
    if (b < MS_N7) {
        const int o = b;
        for (int i = tid; i < 1024; i += 256) sbuf[i] = a.Wa[(size_t)o * 2048 + i];
        __syncthreads();
        for (int j = tid; j < 1024; j += 256) {
            float acc = a.Wa[(size_t)o * 2048 + 1024 + j];
            for (int k = 0; k < 1024; ++k)
                acc = fmaf(sbuf[k], a.Wo[(size_t)k * 1024 + j], acc);
            a.WaF[(size_t)o * 1024 + j] = acc;
        }
        if (tid < 32) {
            float s = 0.f;
            for (int k = tid; k < 1024; k += 32) s += sbuf[k] * a.bo[k];
#pragma unroll
            for (int off = 16; off > 0; off >>= 1)
                s += __shfl_xor_sync(0xffffffffu, s, off);
            if (tid == 0) a.baF[o] = a.ba[o] + s;
        }
        return;
    }
    b -= MS_N7;
    if (b < MS_N8) {
        const int n = b * 8 + (tid >> 5);
        const int lane = tid & 31;
        float s = 0.f;
        for (int k = lane; k < 1024; k += 32) s += a.Wc[(size_t)n * 2048 + k] * a.bo[k];
#pragma unroll
        for (int off = 16; off > 0; off >>= 1)
            s += __shfl_xor_sync(0xffffffffu, s, off);
        if (lane == 0) a.biasG[3072 + n] = a.bc[n] + s;
        return;
    }
    b -= MS_N8;
    if (b < MS_N9) {
        int i = b * 256 + tid;
        a.biasG[i] = a.bhh[i];
        return;
    }
    b -= MS_N9;
    {
        int i = (b * 256 + tid) * 2;
        int m = i >> 10, d = i & 1023;
        float v0 = a.hid[i], v1 = a.hid[i + 1];
        *(float2*)&a.h[i] = make_float2(v0, v1);
        __nv_bfloat162 hv, lv;
        split2(v0, hv.x, lv.x); split2(v1, hv.y, lv.y);
        const size_t off = pa_off(m >> 6, d >> 6, m & 63, (d & 63) * 2);
        *(__nv_bfloat162*)(a.hP + off) = hv;
        *(__nv_bfloat162*)(a.hP + off + 8192) = lv;
    }
}

__global__ void copyf_kernel(const float* __restrict__ s, float* __restrict__ d, int n)
{
    int i = blockIdx.x * 256 + threadIdx.x;
    if (i < n) d[i] = s[i];
}

// ---------------------------------------------------------------------------
extern "C" void kernel_launch(void* const* d_in, const int* in_sizes, int n_in,
                              void* d_out, int out_size)
{
    const float* enc = (const float*)d_in[0];
    const float* hid = (const float*)d_in[1];
    const float* Wa  = (const float*)d_in[3];
    const float* ba  = (const float*)d_in[4];
    const float* Wc  = (const float*)d_in[5];
    const float* bc  = (const float*)d_in[6];
    const float* Wih = (const float*)d_in[7];
    const float* Whh = (const float*)d_in[8];
    const float* bih = (const float*)d_in[9];
    const float* bhh = (const float*)d_in[10];
    const float* Wo  = (const float*)d_in[11];
    const float* bo  = (const float*)d_in[12];

    float* outseq = (float*)d_out;
    float* outh   = outseq + (size_t)BB * TT * HH;

    __nv_bfloat16 *pWoT_hi, *pWoT_lo, *pWc1_hi, *pWc1_lo;
    char *pWihP, *pWhhUP, *pWoP, *pWcBP, *pencP, *pgrP, *phP, *pHallP;
    __half* pencWh;
    float *ph, *pgi, *pghU, *pzero, *pWaF, *pbaF, *pbiasG, *pP;
    cudaGetSymbolAddress((void**)&pWoT_hi, g_WoT_hi); cudaGetSymbolAddress((void**)&pWoT_lo, g_WoT_lo);
    cudaGetSymbolAddress((void**)&pWc1_hi, g_Wc1_hi); cudaGetSymbolAddress((void**)&pWc1_lo, g_Wc1_lo);
    cudaGetSymbolAddress((void**)&pWihP, g_WihP);     cudaGetSymbolAddress((void**)&pWhhUP, g_WhhUP);
    cudaGetSymbolAddress((void**)&pWoP, g_WoP);       cudaGetSymbolAddress((void**)&pWcBP, g_WcBP);
    cudaGetSymbolAddress((void**)&pencP, g_encP);     cudaGetSymbolAddress((void**)&pgrP, g_grP);
    cudaGetSymbolAddress((void**)&phP, g_hP);         cudaGetSymbolAddress((void**)&pHallP, g_HallP);
    cudaGetSymbolAddress((void**)&pencWh, g_encWh);
    cudaGetSymbolAddress((void**)&ph, g_h);           cudaGetSymbolAddress((void**)&pgi, g_gi);
    cudaGetSymbolAddress((void**)&pghU, g_ghU);       cudaGetSymbolAddress((void**)&pzero, g_zero);
    cudaGetSymbolAddress((void**)&pWaF, g_WaF);       cudaGetSymbolAddress((void**)&pbaF, g_baF);
    cudaGetSymbolAddress((void**)&pbiasG, g_biasGhU);
    cudaGetSymbolAddress((void**)&pP, g_P);

    cudaFuncSetAttribute(gemm_std_kernel, cudaFuncAttributeMaxDynamicSharedMemorySize, ENG_SMEM);
    cudaFuncSetAttribute(gemm4_kernel, cudaFuncAttributeMaxDynamicSharedMemorySize, V4_SMEM);
    cudaFuncSetAttribute(stepA_kernel, cudaFuncAttributeMaxDynamicSharedMemorySize, V4_SMEM);
    cudaFuncSetAttribute(stepB_kernel, cudaFuncAttributeMaxDynamicSharedMemorySize, V4_SMEM);

    // ---- launch 1: mega setup ----
    {
        SetupArgs s{};
        s.Wih = Wih; s.Whh = Whh; s.Wo = Wo; s.Wc = Wc; s.enc = enc;
        s.Wa = Wa; s.ba = ba; s.bo = bo; s.bc = bc; s.bhh = bhh; s.hid = hid;
        s.WihP = pWihP; s.WhhUP = pWhhUP; s.WoP = pWoP; s.WcBP = pWcBP;
        s.encP = pencP; s.hP = phP;
        s.WoT_hi = pWoT_hi; s.WoT_lo = pWoT_lo; s.Wc1_hi = pWc1_hi; s.Wc1_lo = pWc1_lo;
        s.WaF = pWaF; s.baF = pbaF; s.biasG = pbiasG; s.h = ph;
        mega_setup_kernel<<<MS_TOTAL, 256>>>(s);
    }
    // ---- launch 2: encW = enc @ WcB^T (v4, M=32768, fp16 output) ----
    gemm4_kernel<<<dim3(8, 512), 256, V4_SMEM>>>(pencP, pWcBP, pzero,
                                                 (float*)pencWh, 1024, 1, 0, 1);
    // ---- launch 3: WcF = Wc1 @ Wo (v3, mode 3: direct pack into WhhUP rows 3072+) ----
    {
        GProb p = { pWc1_hi, pWc1_lo, 1024, pWoT_hi, pWoT_lo, 1024, 1024,
                    pzero, nullptr, 0, (__nv_bfloat16*)pWhhUP, nullptr, 3072, 3 };
        gemm_std_kernel<<<dim3(8, 16), 256, ENG_SMEM>>>(p);
    }

    // ---- decode loop (launch #4 = stepA t=0 -> ncu capture target) ----
    for (int t = 0; t < TT; ++t) {
        {
            StepAArgs a{};
            a.hP = phP; a.WhhUP = pWhhUP; a.biasG = pbiasG; a.ghU = pghU;
            a.h = ph; a.encW = pencWh;
            a.W = (t == 0) ? (Wa + 1024) : pWaF;
            a.wld = (t == 0) ? 2048 : 1024;
            a.bias = (t == 0) ? ba : pbaF;
            a.P = pP;
            stepA_kernel<<<768, 256, V4_SMEM>>>(a);
        }
        gruin_kernel<<<BB * HH / 512, 256>>>(pP, pghU, bc, t, pgrP);
        {
            StepBArgs a{};
            a.grP = pgrP; a.WihP = pWihP; a.bih = bih; a.gi = pgi;
            a.HallP = pHallP; a.WoP = pWoP; a.bo = bo; a.outseq = outseq;
            a.t = t;
            stepB_kernel<<<(t >= 64) ? 256 : 192, 256, V4_SMEM>>>(a);
        }
        gate_kernel<<<BB * HH / 512, 256>>>(pgi, pghU, ph, phP, pHallP, t);
    }

    // ---- tail: odd Hall mtiles of outseq = Hall @ Wo^T + bo ----
    gemm4_kernel<<<dim3(8, 512), 256, V4_SMEM>>>(pHallP, pWoP, bo, outseq, 1024, 2, 1, 0);

    if (out_size >= BB * TT * HH + BB * HH) {
        copyf_kernel<<<BB * HH / 256, 256>>>(ph, outh, BB * HH);
    }
}

// round 16
// speedup vs baseline: 1.3240x; 1.2101x over previous
#include <cuda_runtime.h>
#include <cuda_bf16.h>
#include <cuda_fp16.h>
#include <cstdint>

#define BB 512
#define HH 1024
#define SS 64
#define TT 128

// ---------------------------------------------------------------------------
// Device-global scratch (allocation-free)
// ---------------------------------------------------------------------------
__device__ __align__(256) __nv_bfloat16 g_WoT_hi[1024 * 1024], g_WoT_lo[1024 * 1024];
__device__ __align__(256) __nv_bfloat16 g_Wc1_hi[1024 * 1024], g_Wc1_lo[1024 * 1024];
// folded attention weights
__device__ __align__(256) float g_WaF[64 * 1024];
__device__ __align__(256) float g_baF[64];
__device__ __align__(256) float g_biasGhU[4096];
// v5 W slabs (fp16 single): (ntile,ks) -> 16384 B, rows 128 x cols 64
__device__ __align__(256) char g_WihP[24 * 16 * 16384];
__device__ __align__(256) char g_WhhUP[32 * 16 * 16384];     // [Whh(3072) | WcF(1024)]
__device__ __align__(256) char g_WcBP[8 * 16 * 16384];
// v4 W slab (bf16 hi|lo): (ntile,ks) -> 32768 B  (output GEMM keeps 3-pass)
__device__ __align__(256) char g_WoP[8 * 16 * 32768];
// A slabs: (mtile,ks) -> 16384 B [hi 8K | lo 8K]; fp16 for v5, bf16 for v4
__device__ __align__(256) char g_encP[(size_t)512 * 16 * 16384];    // fp16 hi/lo
__device__ __align__(256) char g_grP[8 * 16 * 16384];               // fp16 hi/lo
__device__ __align__(256) char g_hP[8 * 16 * 16384];                // fp16 hi/lo
__device__ __align__(256) char g_HallP[(size_t)1024 * 16 * 16384];  // bf16 hi/lo
// fp16 encW = enc @ WcB^T
__device__ __align__(256) __half g_encWh[(size_t)32768 * 1024];
// fp32 activations
__device__ __align__(256) float g_P[512 * 1024];
__device__ __align__(256) float g_h[512 * 1024];
__device__ __align__(256) float g_ghU[512 * 4096];           // [gh(3072) | U(1024)]
__device__ __align__(256) float g_gi[512 * 3072];
__device__ __align__(256) float g_zero[4096];

// ---------------------------------------------------------------------------
// Helpers
// ---------------------------------------------------------------------------
__device__ __forceinline__ void split2(float v, __nv_bfloat16& hi, __nv_bfloat16& lo) {
    hi = __float2bfloat16(v);
    lo = __float2bfloat16(v - __bfloat162float(hi));
}
__device__ __forceinline__ void split2h(float v, __half& hi, __half& lo) {
    hi = __float2half_rn(v);
    lo = __float2half_rn(v - __half2float(hi));
}

__device__ __host__ __forceinline__ uint32_t swz(uint32_t off) {
    return off ^ ((off >> 3) & 0x70);
}
__device__ __forceinline__ size_t pa_off(int mt, int ks, int row, int col2) {
    return (size_t)(mt * 16 + ks) * 16384 + swz((uint32_t)(row * 128 + col2));
}
__device__ __forceinline__ size_t pw_off(int nt, int ks, int row, int col2) {   // v4 (32KB)
    return (size_t)(nt * 16 + ks) * 32768 + swz((uint32_t)(row * 128 + col2));
}
__device__ __forceinline__ size_t pw5_off(int nt, int ks, int row, int col2) {  // v5 (16KB)
    return (size_t)(nt * 16 + ks) * 16384 + swz((uint32_t)(row * 128 + col2));
}

__device__ __forceinline__ uint32_t smem_u32(const void* p) {
    uint32_t a;
    asm("{ .reg .u64 t; cvta.to.shared.u64 t, %1; cvt.u32.u64 %0, t; }" : "=r"(a) : "l"(p));
    return a;
}

__device__ __forceinline__ void ldsm_x4(uint32_t* r, uint32_t addr) {
    asm volatile("ldmatrix.sync.aligned.m8n8.x4.shared.b16 {%0,%1,%2,%3}, [%4];\n"
                 : "=r"(r[0]), "=r"(r[1]), "=r"(r[2]), "=r"(r[3]) : "r"(addr));
}

__device__ __forceinline__ void mma_bf16(float* c, const uint32_t* a, const uint32_t* b) {
    asm volatile(
        "mma.sync.aligned.m16n8k16.row.col.f32.bf16.bf16.f32 "
        "{%0,%1,%2,%3}, {%4,%5,%6,%7}, {%8,%9}, {%0,%1,%2,%3};\n"
        : "+f"(c[0]), "+f"(c[1]), "+f"(c[2]), "+f"(c[3])
        : "r"(a[0]), "r"(a[1]), "r"(a[2]), "r"(a[3]), "r"(b[0]), "r"(b[1]));
}
__device__ __forceinline__ void mma_f16(float* c, const uint32_t* a, const uint32_t* b) {
    asm volatile(
        "mma.sync.aligned.m16n8k16.row.col.f32.f16.f16.f32 "
        "{%0,%1,%2,%3}, {%4,%5,%6,%7}, {%8,%9}, {%0,%1,%2,%3};\n"
        : "+f"(c[0]), "+f"(c[1]), "+f"(c[2]), "+f"(c[3])
        : "r"(a[0]), "r"(a[1]), "r"(a[2]), "r"(a[3]), "r"(b[0]), "r"(b[1]));
}

__device__ __forceinline__ void cp16a(uint32_t dst, const void* src) {
    asm volatile("cp.async.cg.shared.global [%0], [%1], 16;\n" :: "r"(dst), "l"(src));
}
#define CP_COMMIT() asm volatile("cp.async.commit_group;\n" ::: "memory")
#define CP_WAIT1()  asm volatile("cp.async.wait_group 1;\n" ::: "memory")

#define MBAR_INIT(mb, c) asm volatile("mbarrier.init.shared.b64 [%0], %1;" :: "r"((uint32_t)(mb)), "r"((uint32_t)(c)) : "memory")
#define EXPECT_TX(mb, n) asm volatile("mbarrier.arrive.expect_tx.shared.b64 _, [%0], %1;" :: "r"((uint32_t)(mb)), "r"((uint32_t)(n)) : "memory")
#define BULK_CP(dst, src, n, mb) \
    asm volatile("cp.async.bulk.shared::cluster.global.mbarrier::complete_tx::bytes [%0], [%1], %2, [%3];" \
        :: "r"((uint32_t)(dst)), "l"(src), "r"((uint32_t)(n)), "r"((uint32_t)(mb)) : "memory")

#define MBAR_WAIT(mb, par) do { \
    uint32_t _m = (uint32_t)(mb); uint32_t _p = (uint32_t)(par); uint32_t _d; \
    asm volatile("{\n\t.reg .pred p;\n\t" \
        "mbarrier.try_wait.parity.acquire.cta.shared::cta.b64 p, [%1], %2;\n\t" \
        "selp.b32 %0, 1, 0, p;\n\t}" : "=r"(_d) : "r"(_m), "r"(_p) : "memory"); \
    if (!_d) { \
        asm volatile("{\n\t.reg .pred P1;\n\t" \
            "WL_%=:\n\t" \
            "mbarrier.try_wait.parity.acquire.cta.shared::cta.b64 P1, [%0], %1, 0x989680;\n\t" \
            "@P1 bra.uni WD_%=;\n\t" \
            "bra.uni WL_%=;\n\t" \
            "WD_%=:\n\t}" :: "r"(_m), "r"(_p) : "memory"); \
    } \
} while (0)

// ---------------------------------------------------------------------------
// Engine v3 (cp.async 16B path) — setup WcF GEMM only (bf16 3-pass accuracy).
// mode 3: output written as SINGLE fp16 into v5 W slab (Chi=slab, ldch=row base)
// ---------------------------------------------------------------------------
struct GProb {
    const __nv_bfloat16 *Ahi, *Alo; int lda;
    const __nv_bfloat16 *Whi, *Wlo; int ldw;
    int K;
    const float* bias;
    float* Cf; int ldc;
    __nv_bfloat16 *Chi, *Clo; int ldch;
    int mode;
};

#define ENG_ALO 9216u
#define ENG_WHI 18432u
#define ENG_WLO 36864u
#define ENG_STAGE 55296u
#define ENG_SMEM 110592

__global__ __launch_bounds__(256, 2) void gemm_std_kernel(GProb p)
{
    extern __shared__ char sm[];
    const uint32_t smbase = smem_u32(sm);
    const int tid = threadIdx.x, warp = tid >> 5, lane = tid & 31;
    const int m0 = blockIdx.y * 64, n0 = blockIdx.x * 128;
    const int S = p.K >> 6;
    const int wm = warp >> 2, wn = warp & 3;
    const int lr = tid >> 1;
    const int lc = (tid & 1) * 4;

    float acc[2][4][4];
#pragma unroll
    for (int mi = 0; mi < 2; ++mi)
#pragma unroll
        for (int nf = 0; nf < 4; ++nf)
#pragma unroll
            for (int q = 0; q < 4; ++q) acc[mi][nf][q] = 0.f;

    const __nv_bfloat16* abase = (lr < 64)
        ? p.Ahi + (size_t)(m0 + lr) * p.lda
        : p.Alo + (size_t)(m0 + lr - 64) * p.lda;
    const __nv_bfloat16* w1base = p.Whi + (size_t)(n0 + lr) * p.ldw;
    const __nv_bfloat16* w2base = p.Wlo + (size_t)(n0 + lr) * p.ldw;
    const uint32_t rowb = (uint32_t)lr * 144 + (uint32_t)lc * 16;

    auto load_stage = [&](int s) {
        const int k0 = (s << 6) + lc * 8;
        const uint32_t sb = smbase + (uint32_t)(s & 1) * ENG_STAGE;
#pragma unroll
        for (int c = 0; c < 4; ++c) cp16a(sb + rowb + c * 16, abase + k0 + c * 8);
#pragma unroll
        for (int c = 0; c < 4; ++c) cp16a(sb + ENG_WHI + rowb + c * 16, w1base + k0 + c * 8);
#pragma unroll
        for (int c = 0; c < 4; ++c) cp16a(sb + ENG_WLO + rowb + c * 16, w2base + k0 + c * 8);
    };

    load_stage(0); CP_COMMIT();
    load_stage(1); CP_COMMIT();

    const int arow = wm * 32 + (lane & 15);
    const int acolb = (lane >> 4) << 3;
    const int g = lane >> 3;
    const int brow = wn * 32 + ((g >> 1) << 3) + (lane & 7);
    const int bcolb = (g & 1) << 3;

    for (int s = 0; s < S; ++s) {
        CP_WAIT1();
        __syncthreads();
        const uint32_t sb = smbase + (uint32_t)(s & 1) * ENG_STAGE;
#pragma unroll
        for (int kk = 0; kk < 4; ++kk) {
            const int acol = kk * 16 + acolb;
            uint32_t ahi[2][4], alo[2][4];
#pragma unroll
            for (int mi = 0; mi < 2; ++mi) {
                const uint32_t off = (uint32_t)((arow + mi * 16) * 144 + acol * 2);
                ldsm_x4(ahi[mi], sb + off);
                ldsm_x4(alo[mi], sb + ENG_ALO + off);
            }
            const int bcol = kk * 16 + bcolb;
            uint32_t bhi[4][2], blo[4][2];
#pragma unroll
            for (int nh = 0; nh < 2; ++nh) {
                uint32_t r[4];
                const uint32_t off = (uint32_t)((brow + nh * 16) * 144 + bcol * 2);
                ldsm_x4(r, sb + ENG_WHI + off);
                bhi[nh * 2 + 0][0] = r[0]; bhi[nh * 2 + 0][1] = r[1];
                bhi[nh * 2 + 1][0] = r[2]; bhi[nh * 2 + 1][1] = r[3];
                ldsm_x4(r, sb + ENG_WLO + off);
                blo[nh * 2 + 0][0] = r[0]; blo[nh * 2 + 0][1] = r[1];
                blo[nh * 2 + 1][0] = r[2]; blo[nh * 2 + 1][1] = r[3];
            }
#pragma unroll
            for (int mi = 0; mi < 2; ++mi)
#pragma unroll
                for (int nf = 0; nf < 4; ++nf)
                    mma_bf16(acc[mi][nf], ahi[mi], bhi[nf]);
#pragma unroll
            for (int mi = 0; mi < 2; ++mi)
#pragma unroll
                for (int nf = 0; nf < 4; ++nf)
                    mma_bf16(acc[mi][nf], ahi[mi], blo[nf]);
#pragma unroll
            for (int mi = 0; mi < 2; ++mi)
#pragma unroll
                for (int nf = 0; nf < 4; ++nf)
                    mma_bf16(acc[mi][nf], alo[mi], bhi[nf]);
        }
        __syncthreads();
        if (s + 2 < S) load_stage(s + 2);
        CP_COMMIT();
    }

    const int row0 = m0 + wm * 32 + (lane >> 2);
    const int col0 = n0 + wn * 32 + ((lane & 3) << 1);
#pragma unroll
    for (int mi = 0; mi < 2; ++mi) {
#pragma unroll
        for (int nf = 0; nf < 4; ++nf) {
            const int col = col0 + nf * 8;
            const float b0 = p.bias[col], b1 = p.bias[col + 1];
#pragma unroll
            for (int half = 0; half < 2; ++half) {
                const int row = row0 + mi * 16 + half * 8;
                float v0 = acc[mi][nf][half * 2 + 0] + b0;
                float v1 = acc[mi][nf][half * 2 + 1] + b1;
                if (p.mode == 0) {
                    *(float2*)&p.Cf[(size_t)row * p.ldc + col] = make_float2(v0, v1);
                } else if (p.mode == 3) {
                    __half2 hv = __floats2half2_rn(v0, v1);
                    char* dst = (char*)p.Chi;
                    const int N = p.ldch + row;
                    *(__half2*)(dst + pw5_off(N >> 7, col >> 6, N & 127, (col & 63) * 2)) = hv;
                }
            }
        }
    }
}

// ---------------------------------------------------------------------------
// v4 GEMM block (bf16 3-pass, 2-stage) — Wo output GEMM only.
// ---------------------------------------------------------------------------
#define V_SMEM 98304

__device__ __forceinline__ void gemm4_block(
    const char* __restrict__ Apack, const char* __restrict__ Wpack,
    const float* __restrict__ bias, float* __restrict__ Cf, int ldc,
    int mtile, int ntile, uint32_t sb0, uint32_t mbb)
{
    const int tid = threadIdx.x, warp = tid >> 5, lane = tid & 31;
    const char* Ab = Apack + (size_t)mtile * 16 * 16384;
    const char* Wb = Wpack + (size_t)ntile * 16 * 32768;
    const uint32_t mb[2] = { mbb, mbb + 8 };

    if (tid == 0) { MBAR_INIT(mb[0], 1); MBAR_INIT(mb[1], 1); }
    __syncthreads();

    auto issue = [&](int s) {
        const uint32_t dst = sb0 + (uint32_t)(s & 1) * 49152u;
        EXPECT_TX(mb[s & 1], 49152u);
        BULK_CP(dst, Ab + (size_t)s * 16384, 16384u, mb[s & 1]);
        BULK_CP(dst + 16384u, Wb + (size_t)s * 32768, 32768u, mb[s & 1]);
    };
    if (tid == 0) { issue(0); issue(1); }

    const int wm = warp >> 2, wn = warp & 3;
    const int arow = wm * 32 + (lane & 15);
    const int acolb = (lane >> 4) << 3;
    const int g = lane >> 3;
    const int brow = wn * 32 + ((g >> 1) << 3) + (lane & 7);
    const int bcolb = (g & 1) << 3;

    float acc[2][4][4];
#pragma unroll
    for (int mi = 0; mi < 2; ++mi)
#pragma unroll
        for (int nf = 0; nf < 4; ++nf)
#pragma unroll
            for (int q = 0; q < 4; ++q) acc[mi][nf][q] = 0.f;

    for (int s = 0; s < 16; ++s) {
        const int b = s & 1;
        MBAR_WAIT(mb[b], (s >> 1) & 1);
        const uint32_t sa = sb0 + (uint32_t)b * 49152u;
        const uint32_t sw = sa + 16384u;
#pragma unroll
        for (int kk = 0; kk < 4; ++kk) {
            const int acol = kk * 16 + acolb;
            uint32_t ahi[2][4], alo[2][4];
#pragma unroll
            for (int mi = 0; mi < 2; ++mi) {
                const uint32_t off = swz((uint32_t)((arow + mi * 16) * 128 + acol * 2));
                ldsm_x4(ahi[mi], sa + off);
                ldsm_x4(alo[mi], sa + 8192u + off);
            }
            const int bcol = kk * 16 + bcolb;
            uint32_t bhi[4][2], blo[4][2];
#pragma unroll
            for (int nh = 0; nh < 2; ++nh) {
                uint32_t r[4];
                const uint32_t off = swz((uint32_t)((brow + nh * 16) * 128 + bcol * 2));
                ldsm_x4(r, sw + off);
                bhi[nh * 2 + 0][0] = r[0]; bhi[nh * 2 + 0][1] = r[1];
                bhi[nh * 2 + 1][0] = r[2]; bhi[nh * 2 + 1][1] = r[3];
                ldsm_x4(r, sw + 16384u + off);
                blo[nh * 2 + 0][0] = r[0]; blo[nh * 2 + 0][1] = r[1];
                blo[nh * 2 + 1][0] = r[2]; blo[nh * 2 + 1][1] = r[3];
            }
#pragma unroll
            for (int mi = 0; mi < 2; ++mi)
#pragma unroll
                for (int nf = 0; nf < 4; ++nf)
                    mma_bf16(acc[mi][nf], ahi[mi], bhi[nf]);
#pragma unroll
            for (int mi = 0; mi < 2; ++mi)
#pragma unroll
                for (int nf = 0; nf < 4; ++nf)
                    mma_bf16(acc[mi][nf], ahi[mi], blo[nf]);
#pragma unroll
            for (int mi = 0; mi < 2; ++mi)
#pragma unroll
                for (int nf = 0; nf < 4; ++nf)
                    mma_bf16(acc[mi][nf], alo[mi], bhi[nf]);
        }
        __syncthreads();
        if (tid == 0 && s + 2 < 16) issue(s + 2);
    }

    const int row0 = mtile * 64 + wm * 32 + (lane >> 2);
    const int col0 = ntile * 128 + wn * 32 + ((lane & 3) << 1);
#pragma unroll
    for (int mi = 0; mi < 2; ++mi) {
#pragma unroll
        for (int nf = 0; nf < 4; ++nf) {
            const int col = col0 + nf * 8;
            const float b0 = bias[col], b1 = bias[col + 1];
#pragma unroll
            for (int half = 0; half < 2; ++half) {
                const int row = row0 + mi * 16 + half * 8;
                *(float2*)&Cf[(size_t)row * ldc + col] =
                    make_float2(acc[mi][nf][half * 2 + 0] + b0,
                                acc[mi][nf][half * 2 + 1] + b1);
            }
        }
    }
}

// ---------------------------------------------------------------------------
// v5 GEMM block: fp16 2-pass (A hi/lo fp16, W single fp16), SAME 2-stage
// protocol as gemm4. Stage = 32 KB (A 16K [hi|lo] + W 16K).
// outmode 0: fp32 out; 1: fp16 out.
// ---------------------------------------------------------------------------
__device__ __forceinline__ void gemm5_block(
    const char* __restrict__ Apack, const char* __restrict__ Wpack,
    const float* __restrict__ bias, float* __restrict__ Cf, int ldc,
    int mtile, int ntile, uint32_t sb0, uint32_t mbb, int outmode)
{
    const int tid = threadIdx.x, warp = tid >> 5, lane = tid & 31;
    const char* Ab = Apack + (size_t)mtile * 16 * 16384;
    const char* Wb = Wpack + (size_t)ntile * 16 * 16384;
    const uint32_t mb[2] = { mbb, mbb + 8 };

    if (tid == 0) { MBAR_INIT(mb[0], 1); MBAR_INIT(mb[1], 1); }
    __syncthreads();

    auto issue = [&](int s) {
        const uint32_t dst = sb0 + (uint32_t)(s & 1) * 32768u;
        EXPECT_TX(mb[s & 1], 32768u);
        BULK_CP(dst, Ab + (size_t)s * 16384, 16384u, mb[s & 1]);
        BULK_CP(dst + 16384u, Wb + (size_t)s * 16384, 16384u, mb[s & 1]);
    };
    if (tid == 0) { issue(0); issue(1); }

    const int wm = warp >> 2, wn = warp & 3;
    const int arow = wm * 32 + (lane & 15);
    const int acolb = (lane >> 4) << 3;
    const int g = lane >> 3;
    const int brow = wn * 32 + ((g >> 1) << 3) + (lane & 7);
    const int bcolb = (g & 1) << 3;

    float acc[2][4][4];
#pragma unroll
    for (int mi = 0; mi < 2; ++mi)
#pragma unroll
        for (int nf = 0; nf < 4; ++nf)
#pragma unroll
            for (int q = 0; q < 4; ++q) acc[mi][nf][q] = 0.f;

    for (int s = 0; s < 16; ++s) {
        const int b = s & 1;
        MBAR_WAIT(mb[b], (s >> 1) & 1);
        const uint32_t sa = sb0 + (uint32_t)b * 32768u;
        const uint32_t sw = sa + 16384u;
#pragma unroll
        for (int kk = 0; kk < 4; ++kk) {
            const int acol = kk * 16 + acolb;
            uint32_t ahi[2][4], alo[2][4];
#pragma unroll
            for (int mi = 0; mi < 2; ++mi) {
                const uint32_t off = swz((uint32_t)((arow + mi * 16) * 128 + acol * 2));
                ldsm_x4(ahi[mi], sa + off);
                ldsm_x4(alo[mi], sa + 8192u + off);
            }
            const int bcol = kk * 16 + bcolb;
            uint32_t bh[4][2];
#pragma unroll
            for (int nh = 0; nh < 2; ++nh) {
                uint32_t r[4];
                const uint32_t off = swz((uint32_t)((brow + nh * 16) * 128 + bcol * 2));
                ldsm_x4(r, sw + off);
                bh[nh * 2 + 0][0] = r[0]; bh[nh * 2 + 0][1] = r[1];
                bh[nh * 2 + 1][0] = r[2]; bh[nh * 2 + 1][1] = r[3];
            }
#pragma unroll
            for (int mi = 0; mi < 2; ++mi)
#pragma unroll
                for (int nf = 0; nf < 4; ++nf)
                    mma_f16(acc[mi][nf], ahi[mi], bh[nf]);
#pragma unroll
            for (int mi = 0; mi < 2; ++mi)
#pragma unroll
                for (int nf = 0; nf < 4; ++nf)
                    mma_f16(acc[mi][nf], alo[mi], bh[nf]);
        }
        __syncthreads();
        if (tid == 0 && s + 2 < 16) issue(s + 2);
    }

    const int row0 = mtile * 64 + wm * 32 + (lane >> 2);
    const int col0 = ntile * 128 + wn * 32 + ((lane & 3) << 1);
#pragma unroll
    for (int mi = 0; mi < 2; ++mi) {
#pragma unroll
        for (int nf = 0; nf < 4; ++nf) {
            const int col = col0 + nf * 8;
            const float b0 = bias[col], b1 = bias[col + 1];
#pragma unroll
            for (int half = 0; half < 2; ++half) {
                const int row = row0 + mi * 16 + half * 8;
                float v0 = acc[mi][nf][half * 2 + 0] + b0;
                float v1 = acc[mi][nf][half * 2 + 1] + b1;
                if (outmode == 0) {
                    *(float2*)&Cf[(size_t)row * ldc + col] = make_float2(v0, v1);
                } else {
                    *(__half2*)&((__half*)Cf)[(size_t)row * ldc + col] =
                        __floats2half2_rn(v0, v1);
                }
            }
        }
    }
}

// generic wrappers; mtile = blockIdx.y * mscale + mbase
__global__ __launch_bounds__(256, 2) void gemm4_kernel(
    const char* __restrict__ Apack, const char* __restrict__ Wpack,
    const float* __restrict__ bias, float* __restrict__ Cf, int ldc,
    int mscale, int mbase)
{
    extern __shared__ char sm[];
    __shared__ uint64_t mbar[2];
    gemm4_block(Apack, Wpack, bias, Cf, ldc,
                blockIdx.y * mscale + mbase, blockIdx.x,
                smem_u32(sm), smem_u32(&mbar[0]));
}

__global__ __launch_bounds__(256, 2) void gemm5_kernel(
    const char* __restrict__ Apack, const char* __restrict__ Wpack,
    const float* __restrict__ bias, float* __restrict__ Cf, int ldc,
    int mscale, int mbase, int outmode)
{
    extern __shared__ char sm[];
    __shared__ uint64_t mbar[2];
    gemm5_block(Apack, Wpack, bias, Cf, ldc,
                blockIdx.y * mscale + mbase, blockIdx.x,
                smem_u32(sm), smem_u32(&mbar[0]), outmode);
}

// ---------------------------------------------------------------------------
// stepA: 768 blocks, interleaved. bid%3==0 -> ghU v5 GEMM tile (bid/3);
// else attention row b = (bid/3)*2 + (bid%3 - 1).
// Attention: EXACT R12 path (1 row / block, 256 thr, uint2 fp16 loads).
// ---------------------------------------------------------------------------
struct StepAArgs {
    const char *hP, *WhhUP;
    const float* biasG;
    float* ghU;
    const float *h;
    const __half* encW;
    const float *W, *bias;
    int wld;
    float* P;
};

__global__ __launch_bounds__(256, 2) void stepA_kernel(StepAArgs a)
{
    extern __shared__ char sm[];
    __shared__ uint64_t mbar[2];
    __shared__ float sh[1024];
    __shared__ float slog[64];
    __shared__ float sw[64];

    const int bid = blockIdx.x;
    const int g3 = bid / 3, r3 = bid - g3 * 3;
    if (r3 == 0) {
        gemm5_block(a.hP, a.WhhUP, a.biasG, a.ghU, 4096,
                    g3 >> 5, g3 & 31, smem_u32(sm), smem_u32(&mbar[0]), 0);
        return;
    }

    // ---- attention: one batch row (R12-proven path) ----
    const int tid = threadIdx.x, warp = tid >> 5, lane = tid & 31;
    const int b = g3 * 2 + (r3 - 1);

    *(float4*)&sh[tid * 4] = *(const float4*)&a.h[(size_t)b * 1024 + tid * 4];
    __syncthreads();

#pragma unroll 1
    for (int j = 0; j < 8; ++j) {
        const int o = warp * 8 + j;
        const float4* w4 = (const float4*)(a.W + (size_t)o * a.wld);
        const float4* t4 = (const float4*)sh;
        float acc = 0.f;
#pragma unroll
        for (int i = 0; i < 8; ++i) {
            float4 wv = w4[lane + (i << 5)];
            float4 tv = t4[lane + (i << 5)];
            acc = fmaf(wv.x, tv.x, fmaf(wv.y, tv.y,
                  fmaf(wv.z, tv.z, fmaf(wv.w, tv.w, acc))));
        }
#pragma unroll
        for (int off = 16; off > 0; off >>= 1)
            acc += __shfl_xor_sync(0xffffffffu, acc, off);
        if (lane == 0) slog[o] = acc + a.bias[o];
    }
    __syncthreads();

    if (warp == 0) {
        float v0 = slog[lane], v1 = slog[lane + 32];
        float m = fmaxf(v0, v1);
#pragma unroll
        for (int off = 16; off > 0; off >>= 1)
            m = fmaxf(m, __shfl_xor_sync(0xffffffffu, m, off));
        float e0 = expf(v0 - m), e1 = expf(v1 - m);
        float s = e0 + e1;
#pragma unroll
        for (int off = 16; off > 0; off >>= 1)
            s += __shfl_xor_sync(0xffffffffu, s, off);
        float inv = 1.f / s;
        sw[lane] = e0 * inv;
        sw[lane + 32] = e1 * inv;
    }
    __syncthreads();

    const uint2* e2 = (const uint2*)(a.encW + (size_t)b * 65536) + tid;
    float4 acc = make_float4(0.f, 0.f, 0.f, 0.f);
#pragma unroll 8
    for (int s = 0; s < SS; ++s) {
        float w = sw[s];
        uint2 ev = e2[s * 256];
        __half2 h01 = *(__half2*)&ev.x;
        __half2 h23 = *(__half2*)&ev.y;
        float2 f01 = __half22float2(h01);
        float2 f23 = __half22float2(h23);
        acc.x = fmaf(w, f01.x, acc.x);
        acc.y = fmaf(w, f01.y, acc.y);
        acc.z = fmaf(w, f23.x, acc.z);
        acc.w = fmaf(w, f23.y, acc.w);
    }
    *(float4*)&a.P[(size_t)b * 1024 + tid * 4] = acc;
}

// ---------------------------------------------------------------------------
// stepB: blocks 0..191 = gi v5 GEMM; blocks 192..255 (t>=64) = early Wo (v4)
// ---------------------------------------------------------------------------
struct StepBArgs {
    const char *grP, *WihP;
    const float* bih;
    float* gi;
    const char *HallP, *WoP;
    const float* bo;
    float* outseq;
    int t;
};

__global__ __launch_bounds__(256, 2) void stepB_kernel(StepBArgs a)
{
    extern __shared__ char sm[];
    __shared__ uint64_t mbar[2];
    const int bid = blockIdx.x;
    if (bid < 192) {
        gemm5_block(a.grP, a.WihP, a.bih, a.gi, 3072,
                    bid / 24, bid % 24, smem_u32(sm), smem_u32(&mbar[0]), 0);
    } else {
        const int idx = (a.t - 64) * 64 + (bid - 192);
        gemm4_block(a.HallP, a.WoP, a.bo, a.outseq, 1024,
                    2 * (idx >> 3), idx & 7, smem_u32(sm), smem_u32(&mbar[0]));
    }
}

// ---------------------------------------------------------------------------
// gruin = relu(P + (t>0 ? U : bc)) -> packed split fp16
// ---------------------------------------------------------------------------
__global__ __launch_bounds__(256) void gruin_kernel(
    const float* __restrict__ P, const float* __restrict__ ghU,
    const float* __restrict__ bc, int t, char* __restrict__ grP)
{
    const int e = (blockIdx.x * 256 + threadIdx.x) * 2;
    const int m = e >> 10, d = e & 1023;
    float a0, a1;
    if (t > 0) {
        const float* u = ghU + (size_t)m * 4096 + 3072 + d;
        a0 = u[0]; a1 = u[1];
    } else { a0 = bc[d]; a1 = bc[d + 1]; }
    float v0 = fmaxf(P[e] + a0, 0.f);
    float v1 = fmaxf(P[e + 1] + a1, 0.f);
    __half2 hv, lv;
    split2h(v0, hv.x, lv.x); split2h(v1, hv.y, lv.y);
    const size_t off = pa_off(m >> 6, d >> 6, m & 63, (d & 63) * 2);
    *(__half2*)(grP + off) = hv;
    *(__half2*)(grP + off + 8192) = lv;
}

// ---------------------------------------------------------------------------
// GRU gates -> h (fp32), hP (fp16 hi/lo), HallP (bf16 hi/lo)
// ---------------------------------------------------------------------------
__global__ __launch_bounds__(256) void gate_kernel(
    const float* __restrict__ gi, const float* __restrict__ ghU,
    float* __restrict__ h, char* __restrict__ hP, char* __restrict__ HallP, int t)
{
    const int e = (blockIdx.x * 256 + threadIdx.x) * 2;
    const int m = e >> 10, d = e & 1023;
    float hn[2];
#pragma unroll
    for (int j = 0; j < 2; ++j) {
        const size_t b3 = (size_t)m * 3072 + d + j;
        const size_t b4 = (size_t)m * 4096 + d + j;
        float r = 1.f / (1.f + expf(-(gi[b3] + ghU[b4])));
        float z = 1.f / (1.f + expf(-(gi[b3 + 1024] + ghU[b4 + 1024])));
        float n = tanhf(gi[b3 + 2048] + r * ghU[b4 + 2048]);
        hn[j] = (1.f - z) * n + z * h[e + j];
    }
    *(float2*)&h[e] = make_float2(hn[0], hn[1]);
    const size_t off = pa_off(m >> 6, d >> 6, m & 63, (d & 63) * 2);
    __half2 hhv, hlv;
    split2h(hn[0], hhv.x, hlv.x); split2h(hn[1], hhv.y, hlv.y);
    *(__half2*)(hP + off) = hhv;
    *(__half2*)(hP + off + 8192) = hlv;
    __nv_bfloat162 bv, blv;
    split2(hn[0], bv.x, blv.x); split2(hn[1], bv.y, blv.y);
    const int M = m * 128 + t;
    const size_t hoff = pa_off(M >> 6, d >> 6, M & 63, (d & 63) * 2);
    *(__nv_bfloat162*)(HallP + hoff) = bv;
    *(__nv_bfloat162*)(HallP + hoff + 8192) = blv;
}

// ---------------------------------------------------------------------------
// Mega setup: split+pack everything, folds, biasG, init h. One launch.
// ---------------------------------------------------------------------------
struct SetupArgs {
    const float *Wih, *Whh, *Wo, *Wc, *enc, *Wa, *ba, *bo, *bc, *bhh, *hid;
    char *WihP, *WhhUP, *WoP, *WcBP, *encP, *hP;
    __nv_bfloat16 *WoT_hi, *WoT_lo, *Wc1_hi, *Wc1_lo;
    float *WaF, *baF, *biasG, *h;
};

// fp32 -> v4 W slab (bf16 hi|lo)
__device__ __forceinline__ void pack_w_f32(const float* src, int ld, int i,
                                           char* dst, int row_base)
{
    const int n = i >> 10, k = i & 1023;
    const float v0 = src[(size_t)n * ld + k];
    const float v1 = src[(size_t)n * ld + k + 1];
    __nv_bfloat162 hv, lv;
    split2(v0, hv.x, lv.x); split2(v1, hv.y, lv.y);
    const int N = n + row_base;
    const size_t off = pw_off(N >> 7, k >> 6, N & 127, (k & 63) * 2);
    *(__nv_bfloat162*)(dst + off) = hv;
    *(__nv_bfloat162*)(dst + off + 16384) = lv;
}
// fp32 -> v5 W slab (fp16 single)
__device__ __forceinline__ void pack_w5_f32(const float* src, int ld, int i,
                                            char* dst, int row_base)
{
    const int n = i >> 10, k = i & 1023;
    __half2 hv = __floats2half2_rn(src[(size_t)n * ld + k], src[(size_t)n * ld + k + 1]);
    const int N = n + row_base;
    *(__half2*)(dst + pw5_off(N >> 7, k >> 6, N & 127, (k & 63) * 2)) = hv;
}

#define MS_N0 6144    // pack Wih (v5 fp16)
#define MS_N1 6144    // pack Whh (v5 fp16)
#define MS_N2 2048    // pack Wo (v4 bf16 hi/lo)
#define MS_N3 1024    // WoT transpose+split (v3)
#define MS_N4 2048    // Wc1 linear split (v3)
#define MS_N5 2048    // pack WcB (v5 fp16)
#define MS_N6 65536   // pack enc (A layout, fp16 hi/lo)
#define MS_N7 64      // fold Wa
#define MS_N8 128     // fold bc -> biasG[3072:]
#define MS_N9 12      // bhh -> biasG[0:3072]
#define MS_N10 1024   // init h
#define MS_TOTAL (MS_N0+MS_N1+MS_N2+MS_N3+MS_N4+MS_N5+MS_N6+MS_N7+MS_N8+MS_N9+MS_N10)

__global__ __launch_bounds__(256) void mega_setup_kernel(SetupArgs a)
{
    __shared__ float sbuf[1088];
    int b = blockIdx.x;
    const int tid = threadIdx.x;

    if (b < MS_N0) { pack_w5_f32(a.Wih, 1024, (b * 256 + tid) * 2, a.WihP, 0); return; }
    b -= MS_N0;
    if (b < MS_N1) { pack_w5_f32(a.Whh, 1024, (b * 256 + tid) * 2, a.WhhUP, 0); return; }
    b -= MS_N1;
    if (b < MS_N2) { pack_w_f32(a.Wo, 1024, (b * 256 + tid) * 2, a.WoP, 0); return; }
    b -= MS_N2;
    if (b < MS_N3) {
        const int bx = (b & 31) * 32, by = (b >> 5) * 32;
        const int tx = tid & 31, ty = tid >> 5;
#pragma unroll
        for (int r = 0; r < 4; ++r)
            sbuf[(ty + 8 * r) * 33 + tx] = a.Wo[(size_t)(by + ty + 8 * r) * 1024 + bx + tx];
        __syncthreads();
#pragma unroll
        for (int r = 0; r < 4; ++r) {
            float v = sbuf[tx * 33 + ty + 8 * r];
            size_t o = (size_t)(bx + ty + 8 * r) * 1024 + by + tx;
            split2(v, a.WoT_hi[o], a.WoT_lo[o]);
        }
        return;
    }
    b -= MS_N3;
    if (b < MS_N4) {
        int i = (b * 256 + tid) * 2;
        int r = i >> 10, c = i & 1023;
        split2(a.Wc[(size_t)r * 2048 + c], a.Wc1_hi[i], a.Wc1_lo[i]);
        split2(a.Wc[(size_t)r * 2048 + c + 1], a.Wc1_hi[i + 1], a.Wc1_lo[i + 1]);
        return;
    }
    b -= MS_N4;
    if (b < MS_N5) { pack_w5_f32(a.Wc + 1024, 2048, (b * 256 + tid) * 2, a.WcBP, 0); return; }
    b -= MS_N5;
    if (b < MS_N6) {
        const size_t i = ((size_t)b * 256 + tid) * 2;
        const int M = (int)(i >> 10), k = (int)(i & 1023);
        __half2 hv, lv;
        split2h(a.enc[i], hv.x, lv.x);
        split2h(a.enc[i + 1], hv.y, lv.y);
        const size_t off = pa_off(M >> 6, k >> 6, M & 63, (k & 63) * 2);
        *(__half2*)(a.encP + off) = hv;
        *(__half2*)(a.encP + off + 8192) = lv;
        return;
    }
    b -= MS_N6;
    if (b < MS_N7) {
        const int o = b;
        for (int i = tid; i < 1024; i += 256) sbuf[i] = a.Wa[(size_t)o * 2048 + i];
        __syncthreads();
        for (int j = tid; j < 1024; j += 256) {
            float acc = a.Wa[(size_t)o * 2048 + 1024 + j];
            for (int k = 0; k < 1024; ++k)
                acc = fmaf(sbuf[k], a.Wo[(size_t)k * 1024 + j], acc);
            a.WaF[(size_t)o * 1024 + j] = acc;
        }
        if (tid < 32) {
            float s = 0.f;
            for (int k = tid; k < 1024; k += 32) s += sbuf[k] * a.bo[k];
#pragma unroll
            for (int off = 16; off > 0; off >>= 1)
                s += __shfl_xor_sync(0xffffffffu, s, off);
            if (tid == 0) a.baF[o] = a.ba[o] + s;
        }
        return;
    }
    b -= MS_N7;
    if (b < MS_N8) {
        const int n = b * 8 + (tid >> 5);
        const int lane = tid & 31;
        float s = 0.f;
        for (int k = lane; k < 1024; k += 32) s += a.Wc[(size_t)n * 2048 + k] * a.bo[k];
#pragma unroll
        for (int off = 16; off > 0; off >>= 1)
            s += __shfl_xor_sync(0xffffffffu, s, off);
        if (lane == 0) a.biasG[3072 + n] = a.bc[n] + s;
        return;
    }
    b -= MS_N8;
    if (b < MS_N9) {
        int i = b * 256 + tid;
        a.biasG[i] = a.bhh[i];
        return;
    }
    b -= MS_N9;
    {
        int i = (b * 256 + tid) * 2;
        int m = i >> 10, d = i & 1023;
        float v0 = a.hid[i], v1 = a.hid[i + 1];
        *(float2*)&a.h[i] = make_float2(v0, v1);
        __half2 hv, lv;
        split2h(v0, hv.x, lv.x); split2h(v1, hv.y, lv.y);
        const size_t off = pa_off(m >> 6, d >> 6, m & 63, (d & 63) * 2);
        *(__half2*)(a.hP + off) = hv;
        *(__half2*)(a.hP + off + 8192) = lv;
    }
}

__global__ void copyf_kernel(const float* __restrict__ s, float* __restrict__ d, int n)
{
    int i = blockIdx.x * 256 + threadIdx.x;
    if (i < n) d[i] = s[i];
}

// ---------------------------------------------------------------------------
extern "C" void kernel_launch(void* const* d_in, const int* in_sizes, int n_in,
                              void* d_out, int out_size)
{
    const float* enc = (const float*)d_in[0];
    const float* hid = (const float*)d_in[1];
    const float* Wa  = (const float*)d_in[3];
    const float* ba  = (const float*)d_in[4];
    const float* Wc  = (const float*)d_in[5];
    const float* bc  = (const float*)d_in[6];
    const float* Wih = (const float*)d_in[7];
    const float* Whh = (const float*)d_in[8];
    const float* bih = (const float*)d_in[9];
    const float* bhh = (const float*)d_in[10];
    const float* Wo  = (const float*)d_in[11];
    const float* bo  = (const float*)d_in[12];

    float* outseq = (float*)d_out;
    float* outh   = outseq + (size_t)BB * TT * HH;

    __nv_bfloat16 *pWoT_hi, *pWoT_lo, *pWc1_hi, *pWc1_lo;
    char *pWihP, *pWhhUP, *pWoP, *pWcBP, *pencP, *pgrP, *phP, *pHallP;
    __half* pencWh;
    float *ph, *pgi, *pghU, *pzero, *pWaF, *pbaF, *pbiasG, *pP;
    cudaGetSymbolAddress((void**)&pWoT_hi, g_WoT_hi); cudaGetSymbolAddress((void**)&pWoT_lo, g_WoT_lo);
    cudaGetSymbolAddress((void**)&pWc1_hi, g_Wc1_hi); cudaGetSymbolAddress((void**)&pWc1_lo, g_Wc1_lo);
    cudaGetSymbolAddress((void**)&pWihP, g_WihP);     cudaGetSymbolAddress((void**)&pWhhUP, g_WhhUP);
    cudaGetSymbolAddress((void**)&pWoP, g_WoP);       cudaGetSymbolAddress((void**)&pWcBP, g_WcBP);
    cudaGetSymbolAddress((void**)&pencP, g_encP);     cudaGetSymbolAddress((void**)&pgrP, g_grP);
    cudaGetSymbolAddress((void**)&phP, g_hP);         cudaGetSymbolAddress((void**)&pHallP, g_HallP);
    cudaGetSymbolAddress((void**)&pencWh, g_encWh);
    cudaGetSymbolAddress((void**)&ph, g_h);           cudaGetSymbolAddress((void**)&pgi, g_gi);
    cudaGetSymbolAddress((void**)&pghU, g_ghU);       cudaGetSymbolAddress((void**)&pzero, g_zero);
    cudaGetSymbolAddress((void**)&pWaF, g_WaF);       cudaGetSymbolAddress((void**)&pbaF, g_baF);
    cudaGetSymbolAddress((void**)&pbiasG, g_biasGhU);
    cudaGetSymbolAddress((void**)&pP, g_P);

    cudaFuncSetAttribute(gemm_std_kernel, cudaFuncAttributeMaxDynamicSharedMemorySize, ENG_SMEM);
    cudaFuncSetAttribute(gemm4_kernel, cudaFuncAttributeMaxDynamicSharedMemorySize, V_SMEM);
    cudaFuncSetAttribute(gemm5_kernel, cudaFuncAttributeMaxDynamicSharedMemorySize, V_SMEM);
    cudaFuncSetAttribute(stepA_kernel, cudaFuncAttributeMaxDynamicSharedMemorySize, V_SMEM);
    cudaFuncSetAttribute(stepB_kernel, cudaFuncAttributeMaxDynamicSharedMemorySize, V_SMEM);

    // ---- launch 1: mega setup ----
    {
        SetupArgs s{};
        s.Wih = Wih; s.Whh = Whh; s.Wo = Wo; s.Wc = Wc; s.enc = enc;
        s.Wa = Wa; s.ba = ba; s.bo = bo; s.bc = bc; s.bhh = bhh; s.hid = hid;
        s.WihP = pWihP; s.WhhUP = pWhhUP; s.WoP = pWoP; s.WcBP = pWcBP;
        s.encP = pencP; s.hP = phP;
        s.WoT_hi = pWoT_hi; s.WoT_lo = pWoT_lo; s.Wc1_hi = pWc1_hi; s.Wc1_lo = pWc1_lo;
        s.WaF = pWaF; s.baF = pbaF; s.biasG = pbiasG; s.h = ph;
        mega_setup_kernel<<<MS_TOTAL, 256>>>(s);
    }
    // ---- launch 2: encW = enc @ WcB^T (v5 2-pass, M=32768, fp16 out) ----
    gemm5_kernel<<<dim3(8, 512), 256, V_SMEM>>>(pencP, pWcBP, pzero,
                                                (float*)pencWh, 1024, 1, 0, 1);
    // ---- launch 3: WcF = Wc1 @ Wo (v3 bf16 3-pass, mode 3: fp16 pack into WhhUP rows 3072+) ----
    {
        GProb p = { pWc1_hi, pWc1_lo, 1024, pWoT_hi, pWoT_lo, 1024, 1024,
                    pzero, nullptr, 0, (__nv_bfloat16*)pWhhUP, nullptr, 3072, 3 };
        gemm_std_kernel<<<dim3(8, 16), 256, ENG_SMEM>>>(p);
    }

    // ---- decode loop (launch #4 = stepA t=0 -> ncu capture target) ----
    for (int t = 0; t < TT; ++t) {
        {
            StepAArgs a{};
            a.hP = phP; a.WhhUP = pWhhUP; a.biasG = pbiasG; a.ghU = pghU;
            a.h = ph; a.encW = pencWh;
            a.W = (t == 0) ? (Wa + 1024) : pWaF;
            a.wld = (t == 0) ? 2048 : 1024;
            a.bias = (t == 0) ? ba : pbaF;
            a.P = pP;
            stepA_kernel<<<768, 256, V_SMEM>>>(a);
        }
        gruin_kernel<<<BB * HH / 512, 256>>>(pP, pghU, bc, t, pgrP);
        {
            StepBArgs a{};
            a.grP = pgrP; a.WihP = pWihP; a.bih = bih; a.gi = pgi;
            a.HallP = pHallP; a.WoP = pWoP; a.bo = bo; a.outseq = outseq;
            a.t = t;
            stepB_kernel<<<(t >= 64) ? 256 : 192, 256, V_SMEM>>>(a);
        }
        gate_kernel<<<BB * HH / 512, 256>>>(pgi, pghU, ph, phP, pHallP, t);
    }

    // ---- tail: odd Hall mtiles of outseq = Hall @ Wo^T + bo (v4 bf16 3-pass) ----
    gemm4_kernel<<<dim3(8, 512), 256, V_SMEM>>>(pHallP, pWoP, bo, outseq, 1024, 2, 1);

    if (out_size >= BB * TT * HH + BB * HH) {
        copyf_kernel<<<BB * HH / 256, 256>>>(ph, outh, BB * HH);
    }
}